// round 12
// baseline (speedup 1.0000x reference)
#include <cuda_runtime.h>
#include <cuda_fp16.h>
#include <math.h>
#include <stdint.h>

// Problem constants
#define BATCH   16384
#define IN_DIM  1280
#define BELLY   1024
#define SCALE_D 512
#define NBINS   100
#define NPAT    10
#define NCAT    1152   // 128 (Wt slot) + 1024 (Wp slot)

// Output layout (float32, concatenated flattened tuple)
#define Z_OFF   ((size_t)0)
#define TL_OFF  ((size_t)BATCH * SCALE_D)
#define PL_OFF  (TL_OFF + (size_t)BATCH * NBINS)
#define TC_OFF  (PL_OFF + (size_t)BATCH * NBINS * NPAT)
#define CV_OFF  (TC_OFF + (size_t)BATCH)

#define XMINF 1e-6f
#define XMAXF ((float)(1.0 - 1e-6))
#define LO_SCALE 2048.0f
#define LO_INV   4.8828125e-4f   // 2^-11, exact

// ---------------------------------------------------------------------------
// Scratch (device globals: allocation-guard safe)
// ---------------------------------------------------------------------------
__device__ __half g_fh[(size_t)BATCH * IN_DIM];
__device__ __half g_fl[(size_t)BATCH * IN_DIM];
__device__ __half g_hh[(size_t)BATCH * BELLY];
__device__ __half g_hl[(size_t)BATCH * BELLY];
__device__ __half g_zh[(size_t)BATCH * SCALE_D];
__device__ __half g_zl[(size_t)BATCH * SCALE_D];
__device__ float  g_zraw[(size_t)BATCH * SCALE_D];
// n-major, k-pair-contiguous weight planes: u32[Npad][K/2]
__device__ uint32_t g_w1h[1024 * (IN_DIM / 2)];
__device__ uint32_t g_w1l[1024 * (IN_DIM / 2)];
__device__ uint32_t g_w2h[512 * (BELLY / 2)];
__device__ uint32_t g_w2l[512 * (BELLY / 2)];
__device__ uint32_t g_wch[NCAT * (SCALE_D / 2)];   // concat Wt|Wp (hi only)
__device__ float    g_bcat[NCAT];
__device__ int      g_maxclass;

// ---------------------------------------------------------------------------
// Helpers
// ---------------------------------------------------------------------------
__device__ __forceinline__ void mma_f32acc(float* d, const uint32_t* a, const uint32_t* b) {
    asm volatile(
        "mma.sync.aligned.m16n8k16.row.col.f32.f16.f16.f32 "
        "{%0,%1,%2,%3}, {%4,%5,%6,%7}, {%8,%9}, {%0,%1,%2,%3};"
        : "+f"(d[0]), "+f"(d[1]), "+f"(d[2]), "+f"(d[3])
        : "r"(a[0]), "r"(a[1]), "r"(a[2]), "r"(a[3]), "r"(b[0]), "r"(b[1]));
}
__device__ __forceinline__ void mma_f16acc(uint32_t* d, const uint32_t* a, const uint32_t* b) {
    asm volatile(
        "mma.sync.aligned.m16n8k16.row.col.f16.f16.f16.f16 "
        "{%0,%1}, {%2,%3,%4,%5}, {%6,%7}, {%0,%1};"
        : "+r"(d[0]), "+r"(d[1])
        : "r"(a[0]), "r"(a[1]), "r"(a[2]), "r"(a[3]), "r"(b[0]), "r"(b[1]));
}
#define LDSM4(r0, r1, r2, r3, addr) \
    asm volatile("ldmatrix.sync.aligned.m8n8.x4.shared.b16 {%0,%1,%2,%3}, [%4];" \
                 : "=r"(r0), "=r"(r1), "=r"(r2), "=r"(r3) : "r"(addr))

// fp16 split with scaled lo plane: x = h + l * 2^-11
__device__ __forceinline__ void split2(float x, __half& h, __half& l) {
    h = __float2half_rn(x);
    l = __float2half_rn((x - __half2float(h)) * LO_SCALE);
}
__device__ __forceinline__ uint64_t pack4h(__half a, __half b, __half c, __half d) {
    union { __half h[4]; uint64_t u; } u;
    u.h[0] = a; u.h[1] = b; u.h[2] = c; u.h[3] = d;
    return u.u;
}
__device__ __forceinline__ uint32_t pack2h(__half a, __half b) {
    union { __half h[2]; uint32_t u; } u;
    u.h[0] = a; u.h[1] = b;
    return u.u;
}
__device__ __forceinline__ uint32_t smem_u32(const void* p) {
    uint32_t a;
    asm("{ .reg .u64 t; cvta.to.shared.u64 t, %1; cvt.u32.u64 %0, t; }"
        : "=r"(a) : "l"(p));
    return a;
}
__device__ __forceinline__ void cp16(uint32_t dst, const void* src) {
    asm volatile("cp.async.cg.shared.global [%0], [%1], 16;"
                 :: "r"(dst), "l"(src));
}
#define CP_COMMIT() asm volatile("cp.async.commit_group;" ::: "memory")
#define CP_WAIT1()  asm volatile("cp.async.wait_group 1;" ::: "memory")
#define CP_WAIT0()  asm volatile("cp.async.wait_group 0;" ::: "memory")

// smem: 4 planes of [128 rows][36 u32] (lo planes unused when !CROSS)
#define SROW_B 144
#define PLANE  18432
#define OFF_AL PLANE
#define OFF_BH (2 * PLANE)
#define OFF_BL (3 * PLANE)
#define BUF_BYTES (4 * PLANE)
#define SM_TOTAL (2 * BUF_BYTES)   // 147456

#define NTHREADS 512

// ---------------------------------------------------------------------------
// fp16 split GEMM on HMMA: C[M,Npad] = op(A@B + bias)
// CROSS=true : 3 products (hh fp32 acc; h.l'+l'.h shared fp16 acc, lo scaled 2^11)
// CROSS=false: 1 product (hh fp32 acc only) — for direct-budget outputs.
// Tile 128x128, BK=64, 512 threads (16 warps = 4M x 4N, warp tile 32x32).
// ---------------------------------------------------------------------------
template<int KCHUNKS, bool CROSS, bool BIAS, bool RELU, bool SPLIT_OUT, bool FUSE>
__global__ __launch_bounds__(NTHREADS)
void tc_gemm(const __half* __restrict__ Ahi,
             const __half* __restrict__ Alo,
             const uint32_t* __restrict__ Bh,
             const uint32_t* __restrict__ Bl,
             const float* __restrict__ bias,
             float* __restrict__ C,
             float* __restrict__ Cpl,
             __half* __restrict__ Chi,
             __half* __restrict__ Clo,
             int N) {
    constexpr int K = KCHUNKS * 64;
    constexpr int KH = K / 2;
    extern __shared__ char smem[];
    const uint32_t sb = smem_u32(smem);

    const int tid = threadIdx.x, wid = tid >> 5, lid = tid & 31;
    const int gid = lid >> 2, tig = lid & 3;
    const int mw = (wid & 3) * 32;
    const int nw = (wid >> 2) * 32;
    const int m0 = blockIdx.y * 128, n0 = blockIdx.x * 128;

    uint32_t aoff[2], boff[2];
#pragma unroll
    for (int mat = 0; mat < 2; mat++) {
        const int r = mw + mat * 16 + (lid & 15);
        const int kc = (lid >> 4) * 4;
        aoff[mat] = (uint32_t)(r * 36 + kc) * 4;
    }
#pragma unroll
    for (int p = 0; p < 2; p++) {
        const int r = nw + p * 16 + (lid & 7) + ((lid & 16) >> 1);
        const int kc = ((lid >> 3) & 1) * 4;
        boff[p] = (uint32_t)(r * 36 + kc) * 4;
    }

    float acc[2][4][4];
    uint32_t accx[2][4][2];
#pragma unroll
    for (int i = 0; i < 2; i++)
#pragma unroll
        for (int j = 0; j < 4; j++) {
#pragma unroll
            for (int q = 0; q < 4; q++) acc[i][j][q] = 0.0f;
            accx[i][j][0] = 0u; accx[i][j][1] = 0u;
        }

    auto fill = [&](int c, uint32_t boffb) {
        const int k0 = c * 64;
#pragma unroll
        for (int i = 0; i < 2; i++) {
            const int idx = tid + i * NTHREADS;
            const int row = idx >> 3, c8 = idx & 7;
            const uint32_t d = sb + boffb + row * SROW_B + c8 * 16;
            const size_t g = (size_t)(m0 + row) * K + k0 + c8 * 8;
            cp16(d, Ahi + g);
            if (CROSS) cp16(d + OFF_AL, Alo + g);
        }
#pragma unroll
        for (int i = 0; i < 2; i++) {
            const int idx = tid + i * NTHREADS;
            const int row = idx >> 3, c8 = idx & 7;
            const uint32_t d = sb + boffb + OFF_BH + row * SROW_B + c8 * 16;
            const size_t g = (size_t)(n0 + row) * KH + (k0 >> 1) + c8 * 4;
            cp16(d, Bh + g);
            if (CROSS) cp16(d + (OFF_BL - OFF_BH), Bl + g);
        }
    };

    fill(0, 0);
    CP_COMMIT();

    for (int c = 0; c < KCHUNKS; c++) {
        if (c + 1 < KCHUNKS) {
            fill(c + 1, (uint32_t)((c + 1) & 1) * BUF_BYTES);
            CP_COMMIT();
            CP_WAIT1();
        } else {
            CP_WAIT0();
        }
        __syncthreads();

        const uint32_t bufb = sb + (uint32_t)(c & 1) * BUF_BYTES;

#pragma unroll
        for (int ks = 0; ks < 4; ks++) {
            const uint32_t kbB = ks * 32;
            uint32_t ah[2][4], al[2][4], bfh[4][2], bfl[4][2];
#pragma unroll
            for (int mat = 0; mat < 2; mat++) {
                LDSM4(ah[mat][0], ah[mat][1], ah[mat][2], ah[mat][3],
                      bufb + aoff[mat] + kbB);
                if (CROSS)
                    LDSM4(al[mat][0], al[mat][1], al[mat][2], al[mat][3],
                          bufb + OFF_AL + aoff[mat] + kbB);
            }
#pragma unroll
            for (int p = 0; p < 2; p++) {
                LDSM4(bfh[2 * p][0], bfh[2 * p][1], bfh[2 * p + 1][0], bfh[2 * p + 1][1],
                      bufb + OFF_BH + boff[p] + kbB);
                if (CROSS)
                    LDSM4(bfl[2 * p][0], bfl[2 * p][1], bfl[2 * p + 1][0], bfl[2 * p + 1][1],
                          bufb + OFF_BL + boff[p] + kbB);
            }
#pragma unroll
            for (int mat = 0; mat < 2; mat++)
#pragma unroll
                for (int nat = 0; nat < 4; nat++) {
                    mma_f32acc(acc[mat][nat], ah[mat], bfh[nat]);
                    if (CROSS) {
                        mma_f16acc(accx[mat][nat], ah[mat], bfl[nat]);
                        mma_f16acc(accx[mat][nat], al[mat], bfh[nat]);
                    }
                }
        }
        __syncthreads();
    }

    // ---- epilogue
#pragma unroll
    for (int mat = 0; mat < 2; mat++) {
        const int r0 = m0 + mw + mat * 16 + gid;
#pragma unroll
        for (int nat = 0; nat < 4; nat++) {
            const int n = n0 + nw + nat * 8 + tig * 2;
            float c0 = acc[mat][nat][0], c1 = acc[mat][nat][1];
            float c2 = acc[mat][nat][2], c3 = acc[mat][nat][3];
            if (CROSS) {
                const __half2 x01 = *reinterpret_cast<__half2*>(&accx[mat][nat][0]);
                const __half2 x23 = *reinterpret_cast<__half2*>(&accx[mat][nat][1]);
                c0 += LO_INV * __low2float(x01);
                c1 += LO_INV * __high2float(x01);
                c2 += LO_INV * __low2float(x23);
                c3 += LO_INV * __high2float(x23);
            }
            if (BIAS) {
                const float bv0 = (n < N) ? bias[n] : 0.0f;
                const float bv1 = (n + 1 < N) ? bias[n + 1] : 0.0f;
                c0 += bv0; c1 += bv1; c2 += bv0; c3 += bv1;
            }
            if (RELU) {
                c0 = fmaxf(c0, 0.0f); c1 = fmaxf(c1, 0.0f);
                c2 = fmaxf(c2, 0.0f); c3 = fmaxf(c3, 0.0f);
            }
            if (FUSE) {
                auto route = [&](int row, int col, float v) {
                    if (col < 128) {
                        if (col < NBINS) C[(size_t)row * NBINS + col] = v;
                    } else {
                        const int nc = col - 128;
                        if (nc < NBINS * NPAT) Cpl[(size_t)row * (NBINS * NPAT) + nc] = v;
                    }
                };
                route(r0, n, c0);     route(r0, n + 1, c1);
                route(r0 + 8, n, c2); route(r0 + 8, n + 1, c3);
            } else if (SPLIT_OUT) {
                __half h0, l0, h1, l1;
                split2(c0, h0, l0); split2(c1, h1, l1);
                *(uint32_t*)(Chi + (size_t)r0 * N + n) = pack2h(h0, h1);
                *(uint32_t*)(Clo + (size_t)r0 * N + n) = pack2h(l0, l1);
                split2(c2, h0, l0); split2(c3, h1, l1);
                *(uint32_t*)(Chi + (size_t)(r0 + 8) * N + n) = pack2h(h0, h1);
                *(uint32_t*)(Clo + (size_t)(r0 + 8) * N + n) = pack2h(l0, l1);
            } else {
                *(float2*)(C + (size_t)r0 * N + n) = make_float2(c0, c1);
                *(float2*)(C + (size_t)(r0 + 8) * N + n) = make_float2(c2, c3);
            }
        }
    }
}

// ---------------------------------------------------------------------------
// Prep kernels
// ---------------------------------------------------------------------------
__global__ void k_split(const float* __restrict__ x, __half* __restrict__ xh,
                        __half* __restrict__ xl, int n4) {
    const int i = blockIdx.x * blockDim.x + threadIdx.x;
    if (i >= n4) return;
    const float4 v = ((const float4*)x)[i];
    __half h0, l0, h1, l1, h2, l2, h3, l3;
    split2(v.x, h0, l0); split2(v.y, h1, l1);
    split2(v.z, h2, l2); split2(v.w, h3, l3);
    ((uint64_t*)xh)[i] = pack4h(h0, h1, h2, h3);
    ((uint64_t*)xl)[i] = pack4h(l0, l1, l2, l3);
}

// W [K][N] fp32 -> n-major k-pair packed u32 [Npad][K/2] hi/lo, zero padded
__global__ void k_pack(const float* __restrict__ W, uint32_t* __restrict__ Wh,
                       uint32_t* __restrict__ Wl, int N, int kh, int total) {
    const int idx = blockIdx.x * blockDim.x + threadIdx.x;
    if (idx >= total) return;
    const int n = idx / kh, kp = idx - n * kh;
    float v0 = 0.0f, v1 = 0.0f;
    if (n < N) {
        v0 = W[(size_t)(2 * kp) * N + n];
        v1 = W[(size_t)(2 * kp + 1) * N + n];
    }
    __half h0, l0, h1, l1;
    split2(v0, h0, l0); split2(v1, h1, l1);
    Wh[idx] = pack2h(h0, h1);
    Wl[idx] = pack2h(l0, l1);
}

// Concat pack (hi plane only): rows 0-127 <- Wt, rows 128-1151 <- Wp; + bcat
__global__ void k_packcat(const float* __restrict__ Wt, const float* __restrict__ bt,
                          const float* __restrict__ Wp, const float* __restrict__ bp,
                          uint32_t* __restrict__ Wh, float* __restrict__ bcat) {
    const int kh = SCALE_D / 2;
    const int idx = blockIdx.x * blockDim.x + threadIdx.x;
    if (idx >= NCAT * kh) return;
    const int r = idx / kh, kp = idx - r * kh;
    const float* W; int n, N;
    if (r < 128) { W = Wt; n = r; N = NBINS; }
    else         { W = Wp; n = r - 128; N = NBINS * NPAT; }
    float v0 = 0.0f, v1 = 0.0f;
    if (n < N) {
        v0 = W[(size_t)(2 * kp) * N + n];
        v1 = W[(size_t)(2 * kp + 1) * N + n];
    }
    Wh[idx] = pack2h(__float2half_rn(v0), __float2half_rn(v1));
    if (kp == 0)
        bcat[r] = (r < 128) ? ((n < NBINS) ? bt[n] : 0.0f)
                            : ((n < NBINS * NPAT) ? bp[n] : 0.0f);
}

// ---------------------------------------------------------------------------
// Exact timestep class + max reduction
// ---------------------------------------------------------------------------
__device__ __forceinline__ int ts_class(int ts) {
    int c = ts / 10;
    return min(max(c, 0), NBINS - 1);
}
__global__ void k_maxclass(const int* __restrict__ ts, int n) {
    int i = blockIdx.x * blockDim.x + threadIdx.x;
    int local = 0;
    for (; i < n; i += gridDim.x * blockDim.x)
        local = max(local, ts_class(ts[i]));
#pragma unroll
    for (int o = 16; o; o >>= 1)
        local = max(local, __shfl_xor_sync(0xffffffffu, local, o));
    if ((threadIdx.x & 31) == 0) atomicMax(&g_maxclass, local);
}

// ---------------------------------------------------------------------------
// Row normalize + cantor (fused): one WARP per row; lane 0 runs the staircase.
// ---------------------------------------------------------------------------
__global__ __launch_bounds__(256)
void k_norm(const float* __restrict__ zraw,
            const float* __restrict__ w_pos,
            const float* __restrict__ b_pos,
            const float* __restrict__ alpha_p,
            const int* __restrict__ timesteps,
            float* __restrict__ out_z,
            __half* __restrict__ zh,
            __half* __restrict__ zl,
            float* __restrict__ out_tc,
            float* __restrict__ out_cv) {
    const int lid = threadIdx.x & 31;
    const int row = blockIdx.x * 8 + (threadIdx.x >> 5);

    const float4* zr = (const float4*)(zraw + (size_t)row * SCALE_D);
    const float4* wp = (const float4*)w_pos;

    float4 zv[4];
    float ss = 0.0f;
#pragma unroll
    for (int i = 0; i < 4; i++) {
        zv[i] = zr[lid + 32 * i];
        ss += zv[i].x * zv[i].x + zv[i].y * zv[i].y +
              zv[i].z * zv[i].z + zv[i].w * zv[i].w;
    }
#pragma unroll
    for (int o = 16; o; o >>= 1)
        ss += __shfl_xor_sync(0xffffffffu, ss, o);

    const float nrm = fmaxf(__fsqrt_rn(ss), 1e-12f);

    float4* zo = (float4*)(out_z + (size_t)row * SCALE_D);
    float dd = 0.0f;
#pragma unroll
    for (int i = 0; i < 4; i++) {
        float4 o;
        const float4 wv = wp[lid + 32 * i];
        o.x = __fdiv_rn(zv[i].x, nrm);
        o.y = __fdiv_rn(zv[i].y, nrm);
        o.z = __fdiv_rn(zv[i].z, nrm);
        o.w = __fdiv_rn(zv[i].w, nrm);
        zo[lid + 32 * i] = o;
        __half h0, l0, h1, l1, h2, l2, h3, l3;
        split2(o.x, h0, l0); split2(o.y, h1, l1);
        split2(o.z, h2, l2); split2(o.w, h3, l3);
        const size_t e = (size_t)row * SCALE_D + (lid + 32 * i) * 4;
        *(uint64_t*)(zh + e) = pack4h(h0, h1, h2, h3);
        *(uint64_t*)(zl + e) = pack4h(l0, l1, l2, l3);
        dd += o.x * wv.x + o.y * wv.y + o.z * wv.z + o.w * wv.w;
    }
#pragma unroll
    for (int o = 16; o; o >>= 1)
        dd += __shfl_xor_sync(0xffffffffu, dd, o);

    if (lid == 0) {
        // ---- cantor staircase (numerics identical since R4)
        const int cls = ts_class(timesteps[row]);
        const int max_pos = g_maxclass + 1;
        const float denom = (float)max(max_pos - 1, 1);
        const float pos_f = (float)cls;
        float x = (max_pos > 1) ? __fdiv_rn(pos_f, denom) : pos_f;
        x = fminf(fmaxf(x, XMINF), XMAXF);

        const float pre = __fadd_rn(dd, b_pos[0]);
        const float shift = __fmul_rn((float)tanh((double)pre), 0.3f);
        x = fminf(fmaxf(__fadd_rn(x, shift), XMINF), XMAXF);

        const double alpha = (double)(*alpha_p);
        const float tau_d = __fadd_rn(0.25f, 1e-8f);
        double Cx = 0.0;
        double w = 0.5;
#pragma unroll
        for (int L = 0; L < 12; L++) {
            const float y = __fmul_rn(x, 3.0f);
            const float d0 = __fadd_rn(y, -0.5f);
            const float d1 = __fadd_rn(y, -1.5f);
            const float d2 = __fadd_rn(y, -2.5f);
            const float l0 = __fdiv_rn(-__fmul_rn(d0, d0), tau_d);
            const float l1 = __fdiv_rn(-__fmul_rn(d1, d1), tau_d);
            const float l2 = __fdiv_rn(-__fmul_rn(d2, d2), tau_d);
            const float m = fmaxf(l0, fmaxf(l1, l2));
            const double e0 = exp((double)__fadd_rn(l0, -m));
            const double e1 = exp((double)__fadd_rn(l1, -m));
            const double e2 = exp((double)__fadd_rn(l2, -m));
            const double inv_s = 1.0 / (e0 + e1 + e2);
            const double bit = e1 * inv_s * alpha + e2 * inv_s;
            Cx += bit * w;
            w *= 0.5;
            x = __fadd_rn(y, -floorf(y));
        }
        out_tc[row] = (float)cls;
        float cvf = (float)Cx;
        out_cv[row] = fminf(fmaxf(cvf, 0.0f), 1.0f);
    }
}

// ---------------------------------------------------------------------------
// Launch  (GEMM1 is the 6th launch -> ncu -s 5 -c 1 profiles it)
// ---------------------------------------------------------------------------
extern "C" void kernel_launch(void* const* d_in, const int* in_sizes, int n_in,
                              void* d_out, int out_size) {
    const float* features = (const float*)d_in[0];
    const int*   timesteps = (const int*)d_in[1];
    const float* W1    = (const float*)d_in[2];
    const float* b1    = (const float*)d_in[3];
    const float* W2    = (const float*)d_in[4];
    const float* Wt    = (const float*)d_in[5];
    const float* bt    = (const float*)d_in[6];
    const float* Wp    = (const float*)d_in[7];
    const float* bp    = (const float*)d_in[8];
    const float* w_pos = (const float*)d_in[9];
    const float* b_pos = (const float*)d_in[10];
    const float* alpha = (const float*)d_in[11];

    float* out = (float*)d_out;
    float* out_z  = out + Z_OFF;
    float* out_tl = out + TL_OFF;
    float* out_pl = out + PL_OFF;
    float* out_tc = out + TC_OFF;
    float* out_cv = out + CV_OFF;

    __half *fh, *fl, *hh, *hl, *zh, *zl;
    uint32_t *w1h, *w1l, *w2h, *w2l, *wch;
    float *zraw, *bcat; void* maxp;
    cudaGetSymbolAddress((void**)&fh, g_fh);   cudaGetSymbolAddress((void**)&fl, g_fl);
    cudaGetSymbolAddress((void**)&hh, g_hh);   cudaGetSymbolAddress((void**)&hl, g_hl);
    cudaGetSymbolAddress((void**)&zh, g_zh);   cudaGetSymbolAddress((void**)&zl, g_zl);
    cudaGetSymbolAddress((void**)&w1h, g_w1h); cudaGetSymbolAddress((void**)&w1l, g_w1l);
    cudaGetSymbolAddress((void**)&w2h, g_w2h); cudaGetSymbolAddress((void**)&w2l, g_w2l);
    cudaGetSymbolAddress((void**)&wch, g_wch);
    cudaGetSymbolAddress((void**)&bcat, g_bcat);
    cudaGetSymbolAddress((void**)&zraw, g_zraw);
    cudaGetSymbolAddress(&maxp, g_maxclass);

    auto* g1  = tc_gemm<IN_DIM / 64, true, true, true, true, false>;
    auto* g2  = tc_gemm<BELLY / 64, true, false, false, false, false>;
    auto* g34 = tc_gemm<SCALE_D / 64, false, true, false, false, true>;  // single-product
    cudaFuncSetAttribute(g1,  cudaFuncAttributeMaxDynamicSharedMemorySize, SM_TOTAL);
    cudaFuncSetAttribute(g2,  cudaFuncAttributeMaxDynamicSharedMemorySize, SM_TOTAL);
    cudaFuncSetAttribute(g34, cudaFuncAttributeMaxDynamicSharedMemorySize, SM_TOTAL);

    cudaMemsetAsync(maxp, 0, sizeof(int), 0);          // 1
    k_maxclass<<<32, 256>>>(timesteps, BATCH);         // 2

    const int n4 = BATCH * IN_DIM / 4;
    k_split<<<(n4 + 255) / 256, 256>>>(features, fh, fl, n4);                 // 3
    const int t1 = 1024 * (IN_DIM / 2);
    k_pack<<<(t1 + 255) / 256, 256>>>(W1, w1h, w1l, BELLY, IN_DIM / 2, t1);   // 4
    const int t2 = 512 * (BELLY / 2);
    k_pack<<<(t2 + 255) / 256, 256>>>(W2, w2h, w2l, SCALE_D, BELLY / 2, t2);  // 5

    // GEMM1 (6th launch, profiled): h(split) = relu(features @ W1 + b1)
    g1<<<dim3(BELLY / 128, BATCH / 128), NTHREADS, SM_TOTAL>>>(
        fh, fl, w1h, w1l, b1, nullptr, nullptr, hh, hl, BELLY);

    // GEMM2: zraw = h @ W2
    g2<<<dim3(SCALE_D / 128, BATCH / 128), NTHREADS, SM_TOTAL>>>(
        hh, hl, w2h, w2l, nullptr, zraw, nullptr, nullptr, nullptr, SCALE_D);

    // norm + cantor fused
    k_norm<<<BATCH / 8, 256>>>(zraw, w_pos, b_pos, alpha, timesteps,
                               out_z, zh, zl, out_tc, out_cv);

    const int tc = NCAT * (SCALE_D / 2);
    k_packcat<<<(tc + 255) / 256, 256>>>(Wt, bt, Wp, bp, wch, bcat);

    // Fused GEMM3+GEMM4 (single product): [tl | pl] = zh @ [Wt|Wp]h + [bt|bp]
    g34<<<dim3(NCAT / 128, BATCH / 128), NTHREADS, SM_TOTAL>>>(
        zh, nullptr, wch, nullptr, bcat, out_tl, out_pl, nullptr, nullptr, NCAT);
}

// round 13
// speedup vs baseline: 1.9173x; 1.9173x over previous
#include <cuda_runtime.h>
#include <cuda_fp16.h>
#include <math.h>
#include <stdint.h>

// Problem constants
#define BATCH   16384
#define IN_DIM  1280
#define BELLY   1024
#define SCALE_D 512
#define NBINS   100
#define NPAT    10
#define NCAT    1152   // 128 (Wt slot) + 1024 (Wp slot)

// Output layout (float32, concatenated flattened tuple)
#define Z_OFF   ((size_t)0)
#define TL_OFF  ((size_t)BATCH * SCALE_D)
#define PL_OFF  (TL_OFF + (size_t)BATCH * NBINS)
#define TC_OFF  (PL_OFF + (size_t)BATCH * NBINS * NPAT)
#define CV_OFF  (TC_OFF + (size_t)BATCH)

#define XMINF 1e-6f
#define XMAXF ((float)(1.0 - 1e-6))
#define LO_SCALE 2048.0f
#define LO_INV   4.8828125e-4f   // 2^-11, exact

// ---------------------------------------------------------------------------
// Scratch (device globals: allocation-guard safe)
// ---------------------------------------------------------------------------
__device__ __half g_fh[(size_t)BATCH * IN_DIM];
__device__ __half g_fl[(size_t)BATCH * IN_DIM];
__device__ __half g_hh[(size_t)BATCH * BELLY];
__device__ __half g_hl[(size_t)BATCH * BELLY];
__device__ __half g_zh[(size_t)BATCH * SCALE_D];
__device__ __half g_zl[(size_t)BATCH * SCALE_D];
__device__ float  g_zraw[(size_t)BATCH * SCALE_D];
// n-major, k-pair-contiguous weight planes: u32[Npad][K/2]
__device__ uint32_t g_w1h[1024 * (IN_DIM / 2)];
__device__ uint32_t g_w1l[1024 * (IN_DIM / 2)];
__device__ uint32_t g_w2h[512 * (BELLY / 2)];
__device__ uint32_t g_w2l[512 * (BELLY / 2)];
__device__ uint32_t g_wch[NCAT * (SCALE_D / 2)];   // concat Wt|Wp (hi only)
__device__ float    g_bcat[NCAT];
__device__ float    g_dot[BATCH];
__device__ int      g_maxclass;

// ---------------------------------------------------------------------------
// Helpers
// ---------------------------------------------------------------------------
__device__ __forceinline__ void mma_f32acc(float* d, const uint32_t* a, const uint32_t* b) {
    asm volatile(
        "mma.sync.aligned.m16n8k16.row.col.f32.f16.f16.f32 "
        "{%0,%1,%2,%3}, {%4,%5,%6,%7}, {%8,%9}, {%0,%1,%2,%3};"
        : "+f"(d[0]), "+f"(d[1]), "+f"(d[2]), "+f"(d[3])
        : "r"(a[0]), "r"(a[1]), "r"(a[2]), "r"(a[3]), "r"(b[0]), "r"(b[1]));
}
__device__ __forceinline__ void mma_f16acc(uint32_t* d, const uint32_t* a, const uint32_t* b) {
    asm volatile(
        "mma.sync.aligned.m16n8k16.row.col.f16.f16.f16.f16 "
        "{%0,%1}, {%2,%3,%4,%5}, {%6,%7}, {%0,%1};"
        : "+r"(d[0]), "+r"(d[1])
        : "r"(a[0]), "r"(a[1]), "r"(a[2]), "r"(a[3]), "r"(b[0]), "r"(b[1]));
}
#define LDSM4(r0, r1, r2, r3, addr) \
    asm volatile("ldmatrix.sync.aligned.m8n8.x4.shared.b16 {%0,%1,%2,%3}, [%4];" \
                 : "=r"(r0), "=r"(r1), "=r"(r2), "=r"(r3) : "r"(addr))

// fp16 split with scaled lo plane: x = h + l * 2^-11
__device__ __forceinline__ void split2(float x, __half& h, __half& l) {
    h = __float2half_rn(x);
    l = __float2half_rn((x - __half2float(h)) * LO_SCALE);
}
__device__ __forceinline__ uint64_t pack4h(__half a, __half b, __half c, __half d) {
    union { __half h[4]; uint64_t u; } u;
    u.h[0] = a; u.h[1] = b; u.h[2] = c; u.h[3] = d;
    return u.u;
}
__device__ __forceinline__ uint32_t pack2h(__half a, __half b) {
    union { __half h[2]; uint32_t u; } u;
    u.h[0] = a; u.h[1] = b;
    return u.u;
}
__device__ __forceinline__ uint32_t smem_u32(const void* p) {
    uint32_t a;
    asm("{ .reg .u64 t; cvta.to.shared.u64 t, %1; cvt.u32.u64 %0, t; }"
        : "=r"(a) : "l"(p));
    return a;
}
__device__ __forceinline__ void cp16(uint32_t dst, const void* src) {
    asm volatile("cp.async.cg.shared.global [%0], [%1], 16;"
                 :: "r"(dst), "l"(src));
}
#define CP_COMMIT() asm volatile("cp.async.commit_group;" ::: "memory")
#define CP_WAIT1()  asm volatile("cp.async.wait_group 1;" ::: "memory")
#define CP_WAIT0()  asm volatile("cp.async.wait_group 0;" ::: "memory")

// smem: 4 planes of [128 rows][36 u32] (lo planes unused when !CROSS)
#define SROW_B 144
#define PLANE  18432
#define OFF_AL PLANE
#define OFF_BH (2 * PLANE)
#define OFF_BL (3 * PLANE)
#define BUF_BYTES (4 * PLANE)
#define SM_TOTAL (2 * BUF_BYTES)   // 147456

#define NTHREADS 512

// ---------------------------------------------------------------------------
// fp16 split GEMM on HMMA: C[M,Npad] = op(A@B + bias)
// CROSS=true : 3 products (hh fp32 acc; h.l'+l'.h shared fp16 acc, lo scaled 2^11)
// CROSS=false: 1 product (hh fp32 acc only) — for direct-budget outputs.
// Tile 128x128, BK=64, 512 threads (16 warps = 4M x 4N, warp tile 32x32).
// ---------------------------------------------------------------------------
template<int KCHUNKS, bool CROSS, bool BIAS, bool RELU, bool SPLIT_OUT, bool FUSE>
__global__ __launch_bounds__(NTHREADS)
void tc_gemm(const __half* __restrict__ Ahi,
             const __half* __restrict__ Alo,
             const uint32_t* __restrict__ Bh,
             const uint32_t* __restrict__ Bl,
             const float* __restrict__ bias,
             float* __restrict__ C,
             float* __restrict__ Cpl,
             __half* __restrict__ Chi,
             __half* __restrict__ Clo,
             int N) {
    constexpr int K = KCHUNKS * 64;
    constexpr int KH = K / 2;
    extern __shared__ char smem[];
    const uint32_t sb = smem_u32(smem);

    const int tid = threadIdx.x, wid = tid >> 5, lid = tid & 31;
    const int gid = lid >> 2, tig = lid & 3;
    const int mw = (wid & 3) * 32;
    const int nw = (wid >> 2) * 32;
    const int m0 = blockIdx.y * 128, n0 = blockIdx.x * 128;

    uint32_t aoff[2], boff[2];
#pragma unroll
    for (int mat = 0; mat < 2; mat++) {
        const int r = mw + mat * 16 + (lid & 15);
        const int kc = (lid >> 4) * 4;
        aoff[mat] = (uint32_t)(r * 36 + kc) * 4;
    }
#pragma unroll
    for (int p = 0; p < 2; p++) {
        const int r = nw + p * 16 + (lid & 7) + ((lid & 16) >> 1);
        const int kc = ((lid >> 3) & 1) * 4;
        boff[p] = (uint32_t)(r * 36 + kc) * 4;
    }

    float acc[2][4][4];
    uint32_t accx[2][4][2];
#pragma unroll
    for (int i = 0; i < 2; i++)
#pragma unroll
        for (int j = 0; j < 4; j++) {
#pragma unroll
            for (int q = 0; q < 4; q++) acc[i][j][q] = 0.0f;
            accx[i][j][0] = 0u; accx[i][j][1] = 0u;
        }

    auto fill = [&](int c, uint32_t boffb) {
        const int k0 = c * 64;
#pragma unroll
        for (int i = 0; i < 2; i++) {
            const int idx = tid + i * NTHREADS;
            const int row = idx >> 3, c8 = idx & 7;
            const uint32_t d = sb + boffb + row * SROW_B + c8 * 16;
            const size_t g = (size_t)(m0 + row) * K + k0 + c8 * 8;
            cp16(d, Ahi + g);
            if (CROSS) cp16(d + OFF_AL, Alo + g);
        }
#pragma unroll
        for (int i = 0; i < 2; i++) {
            const int idx = tid + i * NTHREADS;
            const int row = idx >> 3, c8 = idx & 7;
            const uint32_t d = sb + boffb + OFF_BH + row * SROW_B + c8 * 16;
            const size_t g = (size_t)(n0 + row) * KH + (k0 >> 1) + c8 * 4;
            cp16(d, Bh + g);
            if (CROSS) cp16(d + (OFF_BL - OFF_BH), Bl + g);
        }
    };

    fill(0, 0);
    CP_COMMIT();

    for (int c = 0; c < KCHUNKS; c++) {
        if (c + 1 < KCHUNKS) {
            fill(c + 1, (uint32_t)((c + 1) & 1) * BUF_BYTES);
            CP_COMMIT();
            CP_WAIT1();
        } else {
            CP_WAIT0();
        }
        __syncthreads();

        const uint32_t bufb = sb + (uint32_t)(c & 1) * BUF_BYTES;

#pragma unroll
        for (int ks = 0; ks < 4; ks++) {
            const uint32_t kbB = ks * 32;
            uint32_t ah[2][4], al[2][4], bfh[4][2], bfl[4][2];
#pragma unroll
            for (int mat = 0; mat < 2; mat++) {
                LDSM4(ah[mat][0], ah[mat][1], ah[mat][2], ah[mat][3],
                      bufb + aoff[mat] + kbB);
                if (CROSS)
                    LDSM4(al[mat][0], al[mat][1], al[mat][2], al[mat][3],
                          bufb + OFF_AL + aoff[mat] + kbB);
            }
#pragma unroll
            for (int p = 0; p < 2; p++) {
                LDSM4(bfh[2 * p][0], bfh[2 * p][1], bfh[2 * p + 1][0], bfh[2 * p + 1][1],
                      bufb + OFF_BH + boff[p] + kbB);
                if (CROSS)
                    LDSM4(bfl[2 * p][0], bfl[2 * p][1], bfl[2 * p + 1][0], bfl[2 * p + 1][1],
                          bufb + OFF_BL + boff[p] + kbB);
            }
#pragma unroll
            for (int mat = 0; mat < 2; mat++)
#pragma unroll
                for (int nat = 0; nat < 4; nat++) {
                    mma_f32acc(acc[mat][nat], ah[mat], bfh[nat]);
                    if (CROSS) {
                        mma_f16acc(accx[mat][nat], ah[mat], bfl[nat]);
                        mma_f16acc(accx[mat][nat], al[mat], bfh[nat]);
                    }
                }
        }
        __syncthreads();
    }

    // ---- epilogue
#pragma unroll
    for (int mat = 0; mat < 2; mat++) {
        const int r0 = m0 + mw + mat * 16 + gid;
#pragma unroll
        for (int nat = 0; nat < 4; nat++) {
            const int n = n0 + nw + nat * 8 + tig * 2;
            float c0 = acc[mat][nat][0], c1 = acc[mat][nat][1];
            float c2 = acc[mat][nat][2], c3 = acc[mat][nat][3];
            if (CROSS) {
                const __half2 x01 = *reinterpret_cast<__half2*>(&accx[mat][nat][0]);
                const __half2 x23 = *reinterpret_cast<__half2*>(&accx[mat][nat][1]);
                c0 += LO_INV * __low2float(x01);
                c1 += LO_INV * __high2float(x01);
                c2 += LO_INV * __low2float(x23);
                c3 += LO_INV * __high2float(x23);
            }
            if (BIAS) {
                const float bv0 = (n < N) ? bias[n] : 0.0f;
                const float bv1 = (n + 1 < N) ? bias[n + 1] : 0.0f;
                c0 += bv0; c1 += bv1; c2 += bv0; c3 += bv1;
            }
            if (RELU) {
                c0 = fmaxf(c0, 0.0f); c1 = fmaxf(c1, 0.0f);
                c2 = fmaxf(c2, 0.0f); c3 = fmaxf(c3, 0.0f);
            }
            if (FUSE) {
                auto route = [&](int row, int col, float v) {
                    if (col < 128) {
                        if (col < NBINS) C[(size_t)row * NBINS + col] = v;
                    } else {
                        const int nc = col - 128;
                        if (nc < NBINS * NPAT) Cpl[(size_t)row * (NBINS * NPAT) + nc] = v;
                    }
                };
                route(r0, n, c0);     route(r0, n + 1, c1);
                route(r0 + 8, n, c2); route(r0 + 8, n + 1, c3);
            } else if (SPLIT_OUT) {
                __half h0, l0, h1, l1;
                split2(c0, h0, l0); split2(c1, h1, l1);
                *(uint32_t*)(Chi + (size_t)r0 * N + n) = pack2h(h0, h1);
                *(uint32_t*)(Clo + (size_t)r0 * N + n) = pack2h(l0, l1);
                split2(c2, h0, l0); split2(c3, h1, l1);
                *(uint32_t*)(Chi + (size_t)(r0 + 8) * N + n) = pack2h(h0, h1);
                *(uint32_t*)(Clo + (size_t)(r0 + 8) * N + n) = pack2h(l0, l1);
            } else {
                *(float2*)(C + (size_t)r0 * N + n) = make_float2(c0, c1);
                *(float2*)(C + (size_t)(r0 + 8) * N + n) = make_float2(c2, c3);
            }
        }
    }
}

// ---------------------------------------------------------------------------
// Prep kernels
// ---------------------------------------------------------------------------
__global__ void k_split(const float* __restrict__ x, __half* __restrict__ xh,
                        __half* __restrict__ xl, int n4) {
    const int i = blockIdx.x * blockDim.x + threadIdx.x;
    if (i >= n4) return;
    const float4 v = ((const float4*)x)[i];
    __half h0, l0, h1, l1, h2, l2, h3, l3;
    split2(v.x, h0, l0); split2(v.y, h1, l1);
    split2(v.z, h2, l2); split2(v.w, h3, l3);
    ((uint64_t*)xh)[i] = pack4h(h0, h1, h2, h3);
    ((uint64_t*)xl)[i] = pack4h(l0, l1, l2, l3);
}

// W [K][N] fp32 -> n-major k-pair packed u32 [Npad][K/2] hi/lo, zero padded
__global__ void k_pack(const float* __restrict__ W, uint32_t* __restrict__ Wh,
                       uint32_t* __restrict__ Wl, int N, int kh, int total) {
    const int idx = blockIdx.x * blockDim.x + threadIdx.x;
    if (idx >= total) return;
    const int n = idx / kh, kp = idx - n * kh;
    float v0 = 0.0f, v1 = 0.0f;
    if (n < N) {
        v0 = W[(size_t)(2 * kp) * N + n];
        v1 = W[(size_t)(2 * kp + 1) * N + n];
    }
    __half h0, l0, h1, l1;
    split2(v0, h0, l0); split2(v1, h1, l1);
    Wh[idx] = pack2h(h0, h1);
    Wl[idx] = pack2h(l0, l1);
}

// Concat pack (hi plane only): rows 0-127 <- Wt, rows 128-1151 <- Wp; + bcat
__global__ void k_packcat(const float* __restrict__ Wt, const float* __restrict__ bt,
                          const float* __restrict__ Wp, const float* __restrict__ bp,
                          uint32_t* __restrict__ Wh, float* __restrict__ bcat) {
    const int kh = SCALE_D / 2;
    const int idx = blockIdx.x * blockDim.x + threadIdx.x;
    if (idx >= NCAT * kh) return;
    const int r = idx / kh, kp = idx - r * kh;
    const float* W; int n, N;
    if (r < 128) { W = Wt; n = r; N = NBINS; }
    else         { W = Wp; n = r - 128; N = NBINS * NPAT; }
    float v0 = 0.0f, v1 = 0.0f;
    if (n < N) {
        v0 = W[(size_t)(2 * kp) * N + n];
        v1 = W[(size_t)(2 * kp + 1) * N + n];
    }
    Wh[idx] = pack2h(__float2half_rn(v0), __float2half_rn(v1));
    if (kp == 0)
        bcat[r] = (r < 128) ? ((n < NBINS) ? bt[n] : 0.0f)
                            : ((n < NBINS * NPAT) ? bp[n] : 0.0f);
}

// ---------------------------------------------------------------------------
// Exact timestep class + max reduction
// ---------------------------------------------------------------------------
__device__ __forceinline__ int ts_class(int ts) {
    int c = ts / 10;
    return min(max(c, 0), NBINS - 1);
}
__global__ void k_maxclass(const int* __restrict__ ts, int n) {
    int i = blockIdx.x * blockDim.x + threadIdx.x;
    int local = 0;
    for (; i < n; i += gridDim.x * blockDim.x)
        local = max(local, ts_class(ts[i]));
#pragma unroll
    for (int o = 16; o; o >>= 1)
        local = max(local, __shfl_xor_sync(0xffffffffu, local, o));
    if ((threadIdx.x & 31) == 0) atomicMax(&g_maxclass, local);
}

// ---------------------------------------------------------------------------
// Row normalize: one WARP per row; writes z (fp32), z splits (fp16), and dot.
// ---------------------------------------------------------------------------
__global__ __launch_bounds__(256)
void k_norm(const float* __restrict__ zraw,
            const float* __restrict__ w_pos,
            float* __restrict__ out_z,
            __half* __restrict__ zh,
            __half* __restrict__ zl,
            float* __restrict__ out_dot) {
    const int lid = threadIdx.x & 31;
    const int row = blockIdx.x * 8 + (threadIdx.x >> 5);

    const float4* zr = (const float4*)(zraw + (size_t)row * SCALE_D);
    const float4* wp = (const float4*)w_pos;

    float4 zv[4];
    float ss = 0.0f;
#pragma unroll
    for (int i = 0; i < 4; i++) {
        zv[i] = zr[lid + 32 * i];
        ss += zv[i].x * zv[i].x + zv[i].y * zv[i].y +
              zv[i].z * zv[i].z + zv[i].w * zv[i].w;
    }
#pragma unroll
    for (int o = 16; o; o >>= 1)
        ss += __shfl_xor_sync(0xffffffffu, ss, o);

    const float nrm = fmaxf(__fsqrt_rn(ss), 1e-12f);

    float4* zo = (float4*)(out_z + (size_t)row * SCALE_D);
    float dd = 0.0f;
#pragma unroll
    for (int i = 0; i < 4; i++) {
        float4 o;
        const float4 wv = wp[lid + 32 * i];
        o.x = __fdiv_rn(zv[i].x, nrm);
        o.y = __fdiv_rn(zv[i].y, nrm);
        o.z = __fdiv_rn(zv[i].z, nrm);
        o.w = __fdiv_rn(zv[i].w, nrm);
        zo[lid + 32 * i] = o;
        __half h0, l0, h1, l1, h2, l2, h3, l3;
        split2(o.x, h0, l0); split2(o.y, h1, l1);
        split2(o.z, h2, l2); split2(o.w, h3, l3);
        const size_t e = (size_t)row * SCALE_D + (lid + 32 * i) * 4;
        *(uint64_t*)(zh + e) = pack4h(h0, h1, h2, h3);
        *(uint64_t*)(zl + e) = pack4h(l0, l1, l2, l3);
        dd += o.x * wv.x + o.y * wv.y + o.z * wv.z + o.w * wv.w;
    }
#pragma unroll
    for (int o = 16; o; o >>= 1)
        dd += __shfl_xor_sync(0xffffffffu, dd, o);

    if (lid == 0) out_dot[row] = dd;
}

// ---------------------------------------------------------------------------
// Cantor staircase: one THREAD per row (dense warps — all 32 lanes work).
// ---------------------------------------------------------------------------
__global__ __launch_bounds__(256)
void k_cantor(const float* __restrict__ dot,
              const float* __restrict__ b_pos,
              const float* __restrict__ alpha_p,
              const int* __restrict__ timesteps,
              float* __restrict__ out_tc,
              float* __restrict__ out_cv) {
    const int row = blockIdx.x * blockDim.x + threadIdx.x;
    if (row >= BATCH) return;

    const float tot_dd = dot[row];
    const int cls = ts_class(timesteps[row]);

    const int max_pos = g_maxclass + 1;
    const float denom = (float)max(max_pos - 1, 1);
    const float pos_f = (float)cls;
    float x = (max_pos > 1) ? __fdiv_rn(pos_f, denom) : pos_f;
    x = fminf(fmaxf(x, XMINF), XMAXF);

    const float pre = __fadd_rn(tot_dd, b_pos[0]);
    const float shift = __fmul_rn((float)tanh((double)pre), 0.3f);
    x = fminf(fmaxf(__fadd_rn(x, shift), XMINF), XMAXF);

    const double alpha = (double)(*alpha_p);
    const float tau_d = __fadd_rn(0.25f, 1e-8f);
    double Cx = 0.0;
    double w = 0.5;
#pragma unroll
    for (int L = 0; L < 12; L++) {
        const float y = __fmul_rn(x, 3.0f);
        const float d0 = __fadd_rn(y, -0.5f);
        const float d1 = __fadd_rn(y, -1.5f);
        const float d2 = __fadd_rn(y, -2.5f);
        const float l0 = __fdiv_rn(-__fmul_rn(d0, d0), tau_d);
        const float l1 = __fdiv_rn(-__fmul_rn(d1, d1), tau_d);
        const float l2 = __fdiv_rn(-__fmul_rn(d2, d2), tau_d);
        const float m = fmaxf(l0, fmaxf(l1, l2));
        const double e0 = exp((double)__fadd_rn(l0, -m));
        const double e1 = exp((double)__fadd_rn(l1, -m));
        const double e2 = exp((double)__fadd_rn(l2, -m));
        const double inv_s = 1.0 / (e0 + e1 + e2);
        const double bit = e1 * inv_s * alpha + e2 * inv_s;
        Cx += bit * w;
        w *= 0.5;
        x = __fadd_rn(y, -floorf(y));
    }
    out_tc[row] = (float)cls;
    float cvf = (float)Cx;
    out_cv[row] = fminf(fmaxf(cvf, 0.0f), 1.0f);
}

// ---------------------------------------------------------------------------
// Launch  (GEMM1 is the 6th launch -> ncu -s 5 -c 1 profiles it)
// ---------------------------------------------------------------------------
extern "C" void kernel_launch(void* const* d_in, const int* in_sizes, int n_in,
                              void* d_out, int out_size) {
    const float* features = (const float*)d_in[0];
    const int*   timesteps = (const int*)d_in[1];
    const float* W1    = (const float*)d_in[2];
    const float* b1    = (const float*)d_in[3];
    const float* W2    = (const float*)d_in[4];
    const float* Wt    = (const float*)d_in[5];
    const float* bt    = (const float*)d_in[6];
    const float* Wp    = (const float*)d_in[7];
    const float* bp    = (const float*)d_in[8];
    const float* w_pos = (const float*)d_in[9];
    const float* b_pos = (const float*)d_in[10];
    const float* alpha = (const float*)d_in[11];

    float* out = (float*)d_out;
    float* out_z  = out + Z_OFF;
    float* out_tl = out + TL_OFF;
    float* out_pl = out + PL_OFF;
    float* out_tc = out + TC_OFF;
    float* out_cv = out + CV_OFF;

    __half *fh, *fl, *hh, *hl, *zh, *zl;
    uint32_t *w1h, *w1l, *w2h, *w2l, *wch;
    float *zraw, *dot, *bcat; void* maxp;
    cudaGetSymbolAddress((void**)&fh, g_fh);   cudaGetSymbolAddress((void**)&fl, g_fl);
    cudaGetSymbolAddress((void**)&hh, g_hh);   cudaGetSymbolAddress((void**)&hl, g_hl);
    cudaGetSymbolAddress((void**)&zh, g_zh);   cudaGetSymbolAddress((void**)&zl, g_zl);
    cudaGetSymbolAddress((void**)&w1h, g_w1h); cudaGetSymbolAddress((void**)&w1l, g_w1l);
    cudaGetSymbolAddress((void**)&w2h, g_w2h); cudaGetSymbolAddress((void**)&w2l, g_w2l);
    cudaGetSymbolAddress((void**)&wch, g_wch);
    cudaGetSymbolAddress((void**)&bcat, g_bcat);
    cudaGetSymbolAddress((void**)&zraw, g_zraw);
    cudaGetSymbolAddress((void**)&dot, g_dot);
    cudaGetSymbolAddress(&maxp, g_maxclass);

    auto* g1  = tc_gemm<IN_DIM / 64, true, true, true, true, false>;
    auto* g2  = tc_gemm<BELLY / 64, true, false, false, false, false>;
    auto* g34 = tc_gemm<SCALE_D / 64, false, true, false, false, true>;  // single-product
    cudaFuncSetAttribute(g1,  cudaFuncAttributeMaxDynamicSharedMemorySize, SM_TOTAL);
    cudaFuncSetAttribute(g2,  cudaFuncAttributeMaxDynamicSharedMemorySize, SM_TOTAL);
    cudaFuncSetAttribute(g34, cudaFuncAttributeMaxDynamicSharedMemorySize, SM_TOTAL);

    cudaMemsetAsync(maxp, 0, sizeof(int), 0);          // 1
    k_maxclass<<<32, 256>>>(timesteps, BATCH);         // 2

    const int n4 = BATCH * IN_DIM / 4;
    k_split<<<(n4 + 255) / 256, 256>>>(features, fh, fl, n4);                 // 3
    const int t1 = 1024 * (IN_DIM / 2);
    k_pack<<<(t1 + 255) / 256, 256>>>(W1, w1h, w1l, BELLY, IN_DIM / 2, t1);   // 4
    const int t2 = 512 * (BELLY / 2);
    k_pack<<<(t2 + 255) / 256, 256>>>(W2, w2h, w2l, SCALE_D, BELLY / 2, t2);  // 5

    // GEMM1 (6th launch, profiled): h(split) = relu(features @ W1 + b1)
    g1<<<dim3(BELLY / 128, BATCH / 128), NTHREADS, SM_TOTAL>>>(
        fh, fl, w1h, w1l, b1, nullptr, nullptr, hh, hl, BELLY);

    // GEMM2: zraw = h @ W2
    g2<<<dim3(SCALE_D / 128, BATCH / 128), NTHREADS, SM_TOTAL>>>(
        hh, hl, w2h, w2l, nullptr, zraw, nullptr, nullptr, nullptr, SCALE_D);

    // normalize (warp/row, dense) then cantor (thread/row, dense)
    k_norm<<<BATCH / 8, 256>>>(zraw, w_pos, out_z, zh, zl, dot);
    k_cantor<<<(BATCH + 255) / 256, 256>>>(dot, b_pos, alpha, timesteps, out_tc, out_cv);

    const int tc = NCAT * (SCALE_D / 2);
    k_packcat<<<(tc + 255) / 256, 256>>>(Wt, bt, Wp, bp, wch, bcat);

    // Fused GEMM3+GEMM4 (single product): [tl | pl] = zh @ [Wt|Wp]h + [bt|bp]
    g34<<<dim3(NCAT / 128, BATCH / 128), NTHREADS, SM_TOTAL>>>(
        zh, nullptr, wch, nullptr, bcat, out_tl, out_pl, nullptr, nullptr, NCAT);
}

// round 14
// speedup vs baseline: 1.9329x; 1.0082x over previous
#include <cuda_runtime.h>
#include <cuda_fp16.h>
#include <math.h>
#include <stdint.h>

// Problem constants
#define BATCH   16384
#define IN_DIM  1280
#define BELLY   1024
#define SCALE_D 512
#define NBINS   100
#define NPAT    10
#define NCAT    1152   // 128 (Wt slot) + 1024 (Wp slot)

// Output layout (float32, concatenated flattened tuple)
#define Z_OFF   ((size_t)0)
#define TL_OFF  ((size_t)BATCH * SCALE_D)
#define PL_OFF  (TL_OFF + (size_t)BATCH * NBINS)
#define TC_OFF  (PL_OFF + (size_t)BATCH * NBINS * NPAT)
#define CV_OFF  (TC_OFF + (size_t)BATCH)

#define XMINF 1e-6f
#define XMAXF ((float)(1.0 - 1e-6))
#define LO_SCALE 2048.0f
#define LO_INV   4.8828125e-4f   // 2^-11, exact

// ---------------------------------------------------------------------------
// Scratch (device globals: allocation-guard safe)
// ---------------------------------------------------------------------------
__device__ __half g_fh[(size_t)BATCH * IN_DIM];
__device__ __half g_fl[(size_t)BATCH * IN_DIM];
__device__ __half g_hh[(size_t)BATCH * BELLY];
__device__ __half g_hl[(size_t)BATCH * BELLY];
__device__ __half g_zh[(size_t)BATCH * SCALE_D];
__device__ __half g_zl[(size_t)BATCH * SCALE_D];
__device__ float  g_zraw[(size_t)BATCH * SCALE_D];
// n-major, k-pair-contiguous weight planes: u32[Npad][K/2]
__device__ uint32_t g_w1h[1024 * (IN_DIM / 2)];
__device__ uint32_t g_w1l[1024 * (IN_DIM / 2)];
__device__ uint32_t g_w2h[512 * (BELLY / 2)];
__device__ uint32_t g_w2l[512 * (BELLY / 2)];
__device__ uint32_t g_wch[NCAT * (SCALE_D / 2)];   // concat Wt|Wp (hi only)
__device__ float    g_bcat[NCAT];
__device__ float    g_dot[BATCH];
__device__ int      g_maxclass;

// ---------------------------------------------------------------------------
// Helpers
// ---------------------------------------------------------------------------
__device__ __forceinline__ void mma_f32acc(float* d, const uint32_t* a, const uint32_t* b) {
    asm volatile(
        "mma.sync.aligned.m16n8k16.row.col.f32.f16.f16.f32 "
        "{%0,%1,%2,%3}, {%4,%5,%6,%7}, {%8,%9}, {%0,%1,%2,%3};"
        : "+f"(d[0]), "+f"(d[1]), "+f"(d[2]), "+f"(d[3])
        : "r"(a[0]), "r"(a[1]), "r"(a[2]), "r"(a[3]), "r"(b[0]), "r"(b[1]));
}
__device__ __forceinline__ void mma_f16acc(uint32_t* d, const uint32_t* a, const uint32_t* b) {
    asm volatile(
        "mma.sync.aligned.m16n8k16.row.col.f16.f16.f16.f16 "
        "{%0,%1}, {%2,%3,%4,%5}, {%6,%7}, {%0,%1};"
        : "+r"(d[0]), "+r"(d[1])
        : "r"(a[0]), "r"(a[1]), "r"(a[2]), "r"(a[3]), "r"(b[0]), "r"(b[1]));
}
#define LDSM4(r0, r1, r2, r3, addr) \
    asm volatile("ldmatrix.sync.aligned.m8n8.x4.shared.b16 {%0,%1,%2,%3}, [%4];" \
                 : "=r"(r0), "=r"(r1), "=r"(r2), "=r"(r3) : "r"(addr))

// fp16 split with scaled lo plane: x = h + l * 2^-11
__device__ __forceinline__ void split2(float x, __half& h, __half& l) {
    h = __float2half_rn(x);
    l = __float2half_rn((x - __half2float(h)) * LO_SCALE);
}
__device__ __forceinline__ uint64_t pack4h(__half a, __half b, __half c, __half d) {
    union { __half h[4]; uint64_t u; } u;
    u.h[0] = a; u.h[1] = b; u.h[2] = c; u.h[3] = d;
    return u.u;
}
__device__ __forceinline__ uint32_t pack2h(__half a, __half b) {
    union { __half h[2]; uint32_t u; } u;
    u.h[0] = a; u.h[1] = b;
    return u.u;
}
__device__ __forceinline__ uint32_t smem_u32(const void* p) {
    uint32_t a;
    asm("{ .reg .u64 t; cvta.to.shared.u64 t, %1; cvt.u32.u64 %0, t; }"
        : "=r"(a) : "l"(p));
    return a;
}
__device__ __forceinline__ void cp16(uint32_t dst, const void* src) {
    asm volatile("cp.async.cg.shared.global [%0], [%1], 16;"
                 :: "r"(dst), "l"(src));
}
#define CP_COMMIT() asm volatile("cp.async.commit_group;" ::: "memory")
#define CP_WAIT1()  asm volatile("cp.async.wait_group 1;" ::: "memory")
#define CP_WAIT0()  asm volatile("cp.async.wait_group 0;" ::: "memory")

// smem: 4 planes of [128 rows][36 u32] (lo planes unused when !CROSS)
#define SROW_B 144
#define PLANE  18432
#define OFF_AL PLANE
#define OFF_BH (2 * PLANE)
#define OFF_BL (3 * PLANE)
#define BUF_BYTES (4 * PLANE)
#define SM_TOTAL (2 * BUF_BYTES)   // 147456

#define NTHREADS 512

// ---------------------------------------------------------------------------
// fp16 split GEMM on HMMA: C[M,Npad] = op(A@B + bias)
// CROSS=true : 3 products (hh fp32 acc; h.l'+l'.h shared fp16 acc, lo scaled 2^11)
// CROSS=false: 1 product (hh fp32 acc only) — for direct-budget outputs.
// Tile 128x128, BK=64, 512 threads (16 warps = 4M x 4N, warp tile 32x32).
// ---------------------------------------------------------------------------
template<int KCHUNKS, bool CROSS, bool BIAS, bool RELU, bool SPLIT_OUT, bool FUSE>
__global__ __launch_bounds__(NTHREADS)
void tc_gemm(const __half* __restrict__ Ahi,
             const __half* __restrict__ Alo,
             const uint32_t* __restrict__ Bh,
             const uint32_t* __restrict__ Bl,
             const float* __restrict__ bias,
             float* __restrict__ C,
             float* __restrict__ Cpl,
             __half* __restrict__ Chi,
             __half* __restrict__ Clo,
             int N) {
    constexpr int K = KCHUNKS * 64;
    constexpr int KH = K / 2;
    extern __shared__ char smem[];
    const uint32_t sb = smem_u32(smem);

    const int tid = threadIdx.x, wid = tid >> 5, lid = tid & 31;
    const int gid = lid >> 2, tig = lid & 3;
    const int mw = (wid & 3) * 32;
    const int nw = (wid >> 2) * 32;
    const int m0 = blockIdx.y * 128, n0 = blockIdx.x * 128;

    uint32_t aoff[2], boff[2];
#pragma unroll
    for (int mat = 0; mat < 2; mat++) {
        const int r = mw + mat * 16 + (lid & 15);
        const int kc = (lid >> 4) * 4;
        aoff[mat] = (uint32_t)(r * 36 + kc) * 4;
    }
#pragma unroll
    for (int p = 0; p < 2; p++) {
        const int r = nw + p * 16 + (lid & 7) + ((lid & 16) >> 1);
        const int kc = ((lid >> 3) & 1) * 4;
        boff[p] = (uint32_t)(r * 36 + kc) * 4;
    }

    float acc[2][4][4];
    uint32_t accx[2][4][2];
#pragma unroll
    for (int i = 0; i < 2; i++)
#pragma unroll
        for (int j = 0; j < 4; j++) {
#pragma unroll
            for (int q = 0; q < 4; q++) acc[i][j][q] = 0.0f;
            accx[i][j][0] = 0u; accx[i][j][1] = 0u;
        }

    auto fill = [&](int c, uint32_t boffb) {
        const int k0 = c * 64;
#pragma unroll
        for (int i = 0; i < 2; i++) {
            const int idx = tid + i * NTHREADS;
            const int row = idx >> 3, c8 = idx & 7;
            const uint32_t d = sb + boffb + row * SROW_B + c8 * 16;
            const size_t g = (size_t)(m0 + row) * K + k0 + c8 * 8;
            cp16(d, Ahi + g);
            if (CROSS) cp16(d + OFF_AL, Alo + g);
        }
#pragma unroll
        for (int i = 0; i < 2; i++) {
            const int idx = tid + i * NTHREADS;
            const int row = idx >> 3, c8 = idx & 7;
            const uint32_t d = sb + boffb + OFF_BH + row * SROW_B + c8 * 16;
            const size_t g = (size_t)(n0 + row) * KH + (k0 >> 1) + c8 * 4;
            cp16(d, Bh + g);
            if (CROSS) cp16(d + (OFF_BL - OFF_BH), Bl + g);
        }
    };

    fill(0, 0);
    CP_COMMIT();

    for (int c = 0; c < KCHUNKS; c++) {
        if (c + 1 < KCHUNKS) {
            fill(c + 1, (uint32_t)((c + 1) & 1) * BUF_BYTES);
            CP_COMMIT();
            CP_WAIT1();
        } else {
            CP_WAIT0();
        }
        __syncthreads();

        const uint32_t bufb = sb + (uint32_t)(c & 1) * BUF_BYTES;

#pragma unroll
        for (int ks = 0; ks < 4; ks++) {
            const uint32_t kbB = ks * 32;
            uint32_t ah[2][4], al[2][4], bfh[4][2], bfl[4][2];
#pragma unroll
            for (int mat = 0; mat < 2; mat++) {
                LDSM4(ah[mat][0], ah[mat][1], ah[mat][2], ah[mat][3],
                      bufb + aoff[mat] + kbB);
                if (CROSS)
                    LDSM4(al[mat][0], al[mat][1], al[mat][2], al[mat][3],
                          bufb + OFF_AL + aoff[mat] + kbB);
            }
#pragma unroll
            for (int p = 0; p < 2; p++) {
                LDSM4(bfh[2 * p][0], bfh[2 * p][1], bfh[2 * p + 1][0], bfh[2 * p + 1][1],
                      bufb + OFF_BH + boff[p] + kbB);
                if (CROSS)
                    LDSM4(bfl[2 * p][0], bfl[2 * p][1], bfl[2 * p + 1][0], bfl[2 * p + 1][1],
                          bufb + OFF_BL + boff[p] + kbB);
            }
#pragma unroll
            for (int mat = 0; mat < 2; mat++)
#pragma unroll
                for (int nat = 0; nat < 4; nat++) {
                    mma_f32acc(acc[mat][nat], ah[mat], bfh[nat]);
                    if (CROSS) {
                        mma_f16acc(accx[mat][nat], ah[mat], bfl[nat]);
                        mma_f16acc(accx[mat][nat], al[mat], bfh[nat]);
                    }
                }
        }
        __syncthreads();
    }

    // ---- epilogue
#pragma unroll
    for (int mat = 0; mat < 2; mat++) {
        const int r0 = m0 + mw + mat * 16 + gid;
#pragma unroll
        for (int nat = 0; nat < 4; nat++) {
            const int n = n0 + nw + nat * 8 + tig * 2;
            float c0 = acc[mat][nat][0], c1 = acc[mat][nat][1];
            float c2 = acc[mat][nat][2], c3 = acc[mat][nat][3];
            if (CROSS) {
                const __half2 x01 = *reinterpret_cast<__half2*>(&accx[mat][nat][0]);
                const __half2 x23 = *reinterpret_cast<__half2*>(&accx[mat][nat][1]);
                c0 += LO_INV * __low2float(x01);
                c1 += LO_INV * __high2float(x01);
                c2 += LO_INV * __low2float(x23);
                c3 += LO_INV * __high2float(x23);
            }
            if (BIAS) {
                const float bv0 = (n < N) ? bias[n] : 0.0f;
                const float bv1 = (n + 1 < N) ? bias[n + 1] : 0.0f;
                c0 += bv0; c1 += bv1; c2 += bv0; c3 += bv1;
            }
            if (RELU) {
                c0 = fmaxf(c0, 0.0f); c1 = fmaxf(c1, 0.0f);
                c2 = fmaxf(c2, 0.0f); c3 = fmaxf(c3, 0.0f);
            }
            if (FUSE) {
                auto route = [&](int row, int col, float v) {
                    if (col < 128) {
                        if (col < NBINS) C[(size_t)row * NBINS + col] = v;
                    } else {
                        const int nc = col - 128;
                        if (nc < NBINS * NPAT) Cpl[(size_t)row * (NBINS * NPAT) + nc] = v;
                    }
                };
                route(r0, n, c0);     route(r0, n + 1, c1);
                route(r0 + 8, n, c2); route(r0 + 8, n + 1, c3);
            } else if (SPLIT_OUT) {
                __half h0, l0, h1, l1;
                split2(c0, h0, l0); split2(c1, h1, l1);
                *(uint32_t*)(Chi + (size_t)r0 * N + n) = pack2h(h0, h1);
                *(uint32_t*)(Clo + (size_t)r0 * N + n) = pack2h(l0, l1);
                split2(c2, h0, l0); split2(c3, h1, l1);
                *(uint32_t*)(Chi + (size_t)(r0 + 8) * N + n) = pack2h(h0, h1);
                *(uint32_t*)(Clo + (size_t)(r0 + 8) * N + n) = pack2h(l0, l1);
            } else {
                *(float2*)(C + (size_t)r0 * N + n) = make_float2(c0, c1);
                *(float2*)(C + (size_t)(r0 + 8) * N + n) = make_float2(c2, c3);
            }
        }
    }
}

// ---------------------------------------------------------------------------
// Fused prep: one launch does feature split + W1/W2 packs + concat pack.
// Grid-partitioned by flat index; per-item math identical to R13 kernels.
// ---------------------------------------------------------------------------
#define PREP_S0 (BATCH * IN_DIM / 4)                 // feature split (float4 items)
#define PREP_S1 (1024 * (IN_DIM / 2))                // W1 pack
#define PREP_S2 (512 * (BELLY / 2))                  // W2 pack
#define PREP_S3 (NCAT * (SCALE_D / 2))               // concat pack
#define PREP_TOTAL (PREP_S0 + PREP_S1 + PREP_S2 + PREP_S3)

__global__ __launch_bounds__(256)
void k_prep(const float* __restrict__ feat,
            __half* __restrict__ fh, __half* __restrict__ fl,
            const float* __restrict__ W1, uint32_t* __restrict__ w1h, uint32_t* __restrict__ w1l,
            const float* __restrict__ W2, uint32_t* __restrict__ w2h, uint32_t* __restrict__ w2l,
            const float* __restrict__ Wt, const float* __restrict__ bt,
            const float* __restrict__ Wp, const float* __restrict__ bp,
            uint32_t* __restrict__ wch, float* __restrict__ bcat) {
    const int gidx = blockIdx.x * blockDim.x + threadIdx.x;
    if (gidx < PREP_S0) {
        const float4 v = ((const float4*)feat)[gidx];
        __half h0, l0, h1, l1, h2, l2, h3, l3;
        split2(v.x, h0, l0); split2(v.y, h1, l1);
        split2(v.z, h2, l2); split2(v.w, h3, l3);
        ((uint64_t*)fh)[gidx] = pack4h(h0, h1, h2, h3);
        ((uint64_t*)fl)[gidx] = pack4h(l0, l1, l2, l3);
    } else if (gidx < PREP_S0 + PREP_S1) {
        const int idx = gidx - PREP_S0;
        const int kh = IN_DIM / 2;
        const int n = idx / kh, kp = idx - n * kh;   // Npad=1024 == N, no guard
        const float v0 = W1[(size_t)(2 * kp) * BELLY + n];
        const float v1 = W1[(size_t)(2 * kp + 1) * BELLY + n];
        __half h0, l0, h1, l1;
        split2(v0, h0, l0); split2(v1, h1, l1);
        w1h[idx] = pack2h(h0, h1);
        w1l[idx] = pack2h(l0, l1);
    } else if (gidx < PREP_S0 + PREP_S1 + PREP_S2) {
        const int idx = gidx - PREP_S0 - PREP_S1;
        const int kh = BELLY / 2;
        const int n = idx / kh, kp = idx - n * kh;   // Npad=512 == N
        const float v0 = W2[(size_t)(2 * kp) * SCALE_D + n];
        const float v1 = W2[(size_t)(2 * kp + 1) * SCALE_D + n];
        __half h0, l0, h1, l1;
        split2(v0, h0, l0); split2(v1, h1, l1);
        w2h[idx] = pack2h(h0, h1);
        w2l[idx] = pack2h(l0, l1);
    } else if (gidx < PREP_TOTAL) {
        const int idx = gidx - PREP_S0 - PREP_S1 - PREP_S2;
        const int kh = SCALE_D / 2;
        const int r = idx / kh, kp = idx - r * kh;
        const float* W; int n, N;
        if (r < 128) { W = Wt; n = r; N = NBINS; }
        else         { W = Wp; n = r - 128; N = NBINS * NPAT; }
        float v0 = 0.0f, v1 = 0.0f;
        if (n < N) {
            v0 = W[(size_t)(2 * kp) * N + n];
            v1 = W[(size_t)(2 * kp + 1) * N + n];
        }
        wch[idx] = pack2h(__float2half_rn(v0), __float2half_rn(v1));
        if (kp == 0)
            bcat[r] = (r < 128) ? ((n < NBINS) ? bt[n] : 0.0f)
                                : ((n < NBINS * NPAT) ? bp[n] : 0.0f);
    }
}

// ---------------------------------------------------------------------------
// Exact timestep class + single-block max reduction (no memset, no atomics)
// ---------------------------------------------------------------------------
__device__ __forceinline__ int ts_class(int ts) {
    int c = ts / 10;
    return min(max(c, 0), NBINS - 1);
}
__global__ __launch_bounds__(1024)
void k_maxclass(const int* __restrict__ ts) {
    __shared__ int s[32];
    int local = 0;
#pragma unroll
    for (int i = 0; i < BATCH / 1024; i++)
        local = max(local, ts_class(ts[threadIdx.x + i * 1024]));
#pragma unroll
    for (int o = 16; o; o >>= 1)
        local = max(local, __shfl_xor_sync(0xffffffffu, local, o));
    if ((threadIdx.x & 31) == 0) s[threadIdx.x >> 5] = local;
    __syncthreads();
    if (threadIdx.x < 32) {
        int v = s[threadIdx.x];
#pragma unroll
        for (int o = 16; o; o >>= 1)
            v = max(v, __shfl_xor_sync(0xffffffffu, v, o));
        if (threadIdx.x == 0) g_maxclass = v;
    }
}

// ---------------------------------------------------------------------------
// Row normalize: one WARP per row; writes z (fp32), z splits (fp16), and dot.
// ---------------------------------------------------------------------------
__global__ __launch_bounds__(256)
void k_norm(const float* __restrict__ zraw,
            const float* __restrict__ w_pos,
            float* __restrict__ out_z,
            __half* __restrict__ zh,
            __half* __restrict__ zl,
            float* __restrict__ out_dot) {
    const int lid = threadIdx.x & 31;
    const int row = blockIdx.x * 8 + (threadIdx.x >> 5);

    const float4* zr = (const float4*)(zraw + (size_t)row * SCALE_D);
    const float4* wp = (const float4*)w_pos;

    float4 zv[4];
    float ss = 0.0f;
#pragma unroll
    for (int i = 0; i < 4; i++) {
        zv[i] = zr[lid + 32 * i];
        ss += zv[i].x * zv[i].x + zv[i].y * zv[i].y +
              zv[i].z * zv[i].z + zv[i].w * zv[i].w;
    }
#pragma unroll
    for (int o = 16; o; o >>= 1)
        ss += __shfl_xor_sync(0xffffffffu, ss, o);

    const float nrm = fmaxf(__fsqrt_rn(ss), 1e-12f);

    float4* zo = (float4*)(out_z + (size_t)row * SCALE_D);
    float dd = 0.0f;
#pragma unroll
    for (int i = 0; i < 4; i++) {
        float4 o;
        const float4 wv = wp[lid + 32 * i];
        o.x = __fdiv_rn(zv[i].x, nrm);
        o.y = __fdiv_rn(zv[i].y, nrm);
        o.z = __fdiv_rn(zv[i].z, nrm);
        o.w = __fdiv_rn(zv[i].w, nrm);
        zo[lid + 32 * i] = o;
        __half h0, l0, h1, l1, h2, l2, h3, l3;
        split2(o.x, h0, l0); split2(o.y, h1, l1);
        split2(o.z, h2, l2); split2(o.w, h3, l3);
        const size_t e = (size_t)row * SCALE_D + (lid + 32 * i) * 4;
        *(uint64_t*)(zh + e) = pack4h(h0, h1, h2, h3);
        *(uint64_t*)(zl + e) = pack4h(l0, l1, l2, l3);
        dd += o.x * wv.x + o.y * wv.y + o.z * wv.z + o.w * wv.w;
    }
#pragma unroll
    for (int o = 16; o; o >>= 1)
        dd += __shfl_xor_sync(0xffffffffu, dd, o);

    if (lid == 0) out_dot[row] = dd;
}

// ---------------------------------------------------------------------------
// Cantor staircase: one THREAD per row (dense warps).
// ---------------------------------------------------------------------------
__global__ __launch_bounds__(256)
void k_cantor(const float* __restrict__ dot,
              const float* __restrict__ b_pos,
              const float* __restrict__ alpha_p,
              const int* __restrict__ timesteps,
              float* __restrict__ out_tc,
              float* __restrict__ out_cv) {
    const int row = blockIdx.x * blockDim.x + threadIdx.x;
    if (row >= BATCH) return;

    const float tot_dd = dot[row];
    const int cls = ts_class(timesteps[row]);

    const int max_pos = g_maxclass + 1;
    const float denom = (float)max(max_pos - 1, 1);
    const float pos_f = (float)cls;
    float x = (max_pos > 1) ? __fdiv_rn(pos_f, denom) : pos_f;
    x = fminf(fmaxf(x, XMINF), XMAXF);

    const float pre = __fadd_rn(tot_dd, b_pos[0]);
    const float shift = __fmul_rn((float)tanh((double)pre), 0.3f);
    x = fminf(fmaxf(__fadd_rn(x, shift), XMINF), XMAXF);

    const double alpha = (double)(*alpha_p);
    const float tau_d = __fadd_rn(0.25f, 1e-8f);
    double Cx = 0.0;
    double w = 0.5;
#pragma unroll
    for (int L = 0; L < 12; L++) {
        const float y = __fmul_rn(x, 3.0f);
        const float d0 = __fadd_rn(y, -0.5f);
        const float d1 = __fadd_rn(y, -1.5f);
        const float d2 = __fadd_rn(y, -2.5f);
        const float l0 = __fdiv_rn(-__fmul_rn(d0, d0), tau_d);
        const float l1 = __fdiv_rn(-__fmul_rn(d1, d1), tau_d);
        const float l2 = __fdiv_rn(-__fmul_rn(d2, d2), tau_d);
        const float m = fmaxf(l0, fmaxf(l1, l2));
        const double e0 = exp((double)__fadd_rn(l0, -m));
        const double e1 = exp((double)__fadd_rn(l1, -m));
        const double e2 = exp((double)__fadd_rn(l2, -m));
        const double inv_s = 1.0 / (e0 + e1 + e2);
        const double bit = e1 * inv_s * alpha + e2 * inv_s;
        Cx += bit * w;
        w *= 0.5;
        x = __fadd_rn(y, -floorf(y));
    }
    out_tc[row] = (float)cls;
    float cvf = (float)Cx;
    out_cv[row] = fminf(fmaxf(cvf, 0.0f), 1.0f);
}

// ---------------------------------------------------------------------------
// Launch  (7 graph nodes; GEMM34 is the 6th -> ncu -s 5 -c 1 profiles a GEMM)
// ---------------------------------------------------------------------------
extern "C" void kernel_launch(void* const* d_in, const int* in_sizes, int n_in,
                              void* d_out, int out_size) {
    const float* features = (const float*)d_in[0];
    const int*   timesteps = (const int*)d_in[1];
    const float* W1    = (const float*)d_in[2];
    const float* b1    = (const float*)d_in[3];
    const float* W2    = (const float*)d_in[4];
    const float* Wt    = (const float*)d_in[5];
    const float* bt    = (const float*)d_in[6];
    const float* Wp    = (const float*)d_in[7];
    const float* bp    = (const float*)d_in[8];
    const float* w_pos = (const float*)d_in[9];
    const float* b_pos = (const float*)d_in[10];
    const float* alpha = (const float*)d_in[11];

    float* out = (float*)d_out;
    float* out_z  = out + Z_OFF;
    float* out_tl = out + TL_OFF;
    float* out_pl = out + PL_OFF;
    float* out_tc = out + TC_OFF;
    float* out_cv = out + CV_OFF;

    __half *fh, *fl, *hh, *hl, *zh, *zl;
    uint32_t *w1h, *w1l, *w2h, *w2l, *wch;
    float *zraw, *dot, *bcat;
    cudaGetSymbolAddress((void**)&fh, g_fh);   cudaGetSymbolAddress((void**)&fl, g_fl);
    cudaGetSymbolAddress((void**)&hh, g_hh);   cudaGetSymbolAddress((void**)&hl, g_hl);
    cudaGetSymbolAddress((void**)&zh, g_zh);   cudaGetSymbolAddress((void**)&zl, g_zl);
    cudaGetSymbolAddress((void**)&w1h, g_w1h); cudaGetSymbolAddress((void**)&w1l, g_w1l);
    cudaGetSymbolAddress((void**)&w2h, g_w2h); cudaGetSymbolAddress((void**)&w2l, g_w2l);
    cudaGetSymbolAddress((void**)&wch, g_wch);
    cudaGetSymbolAddress((void**)&bcat, g_bcat);
    cudaGetSymbolAddress((void**)&zraw, g_zraw);
    cudaGetSymbolAddress((void**)&dot, g_dot);

    auto* g1  = tc_gemm<IN_DIM / 64, true, true, true, true, false>;
    auto* g2  = tc_gemm<BELLY / 64, true, false, false, false, false>;
    auto* g34 = tc_gemm<SCALE_D / 64, false, true, false, false, true>;  // single-product
    cudaFuncSetAttribute(g1,  cudaFuncAttributeMaxDynamicSharedMemorySize, SM_TOTAL);
    cudaFuncSetAttribute(g2,  cudaFuncAttributeMaxDynamicSharedMemorySize, SM_TOTAL);
    cudaFuncSetAttribute(g34, cudaFuncAttributeMaxDynamicSharedMemorySize, SM_TOTAL);

    // 1) max timestep class (single block, direct store)
    k_maxclass<<<1, 1024>>>(timesteps);

    // 2) fused prep: split features + pack W1/W2 + concat-pack Wt|Wp
    k_prep<<<(PREP_TOTAL + 255) / 256, 256>>>(
        features, fh, fl, W1, w1h, w1l, W2, w2h, w2l,
        Wt, bt, Wp, bp, wch, bcat);

    // 3) GEMM1: h(split) = relu(features @ W1 + b1)
    g1<<<dim3(BELLY / 128, BATCH / 128), NTHREADS, SM_TOTAL>>>(
        fh, fl, w1h, w1l, b1, nullptr, nullptr, hh, hl, BELLY);

    // 4) GEMM2: zraw = h @ W2
    g2<<<dim3(SCALE_D / 128, BATCH / 128), NTHREADS, SM_TOTAL>>>(
        hh, hl, w2h, w2l, nullptr, zraw, nullptr, nullptr, nullptr, SCALE_D);

    // 5) normalize (warp/row, dense)
    k_norm<<<BATCH / 8, 256>>>(zraw, w_pos, out_z, zh, zl, dot);

    // 6) fused GEMM3+GEMM4 (single product) — profiled launch
    g34<<<dim3(NCAT / 128, BATCH / 128), NTHREADS, SM_TOTAL>>>(
        zh, nullptr, wch, nullptr, bcat, out_tl, out_pl, nullptr, nullptr, NCAT);

    // 7) cantor (thread/row, dense)
    k_cantor<<<(BATCH + 255) / 256, 256>>>(dot, b_pos, alpha, timesteps, out_tc, out_cv);
}

// round 15
// speedup vs baseline: 2.1065x; 1.0898x over previous
#include <cuda_runtime.h>
#include <cuda_fp16.h>
#include <math.h>
#include <stdint.h>

// Problem constants
#define BATCH   16384
#define IN_DIM  1280
#define BELLY   1024
#define SCALE_D 512
#define NBINS   100
#define NPAT    10
#define NCAT    1152   // 128 (Wt slot) + 1024 (Wp slot)

// Output layout (float32, concatenated flattened tuple)
#define Z_OFF   ((size_t)0)
#define TL_OFF  ((size_t)BATCH * SCALE_D)
#define PL_OFF  (TL_OFF + (size_t)BATCH * NBINS)
#define TC_OFF  (PL_OFF + (size_t)BATCH * NBINS * NPAT)
#define CV_OFF  (TC_OFF + (size_t)BATCH)

#define XMINF 1e-6f
#define XMAXF ((float)(1.0 - 1e-6))
#define LO_SCALE 2048.0f
#define LO_INV   4.8828125e-4f   // 2^-11, exact

// ---------------------------------------------------------------------------
// Scratch (device globals: allocation-guard safe)
// ---------------------------------------------------------------------------
__device__ __half g_fh[(size_t)BATCH * IN_DIM];
__device__ __half g_fl[(size_t)BATCH * IN_DIM];
__device__ __half g_hh[(size_t)BATCH * BELLY];
__device__ __half g_hl[(size_t)BATCH * BELLY];
__device__ __half g_zh[(size_t)BATCH * SCALE_D];
__device__ __half g_zl[(size_t)BATCH * SCALE_D];
__device__ float  g_zraw[(size_t)BATCH * SCALE_D];
// n-major, k-pair-contiguous weight planes: u32[Npad][K/2]
__device__ uint32_t g_w1h[1024 * (IN_DIM / 2)];
__device__ uint32_t g_w1l[1024 * (IN_DIM / 2)];
__device__ uint32_t g_w2h[512 * (BELLY / 2)];
__device__ uint32_t g_w2l[512 * (BELLY / 2)];
__device__ uint32_t g_wch[NCAT * (SCALE_D / 2)];   // concat Wt|Wp (hi only)
__device__ float    g_bcat[NCAT];
__device__ float    g_dot[BATCH];
__device__ int      g_maxclass;

// ---------------------------------------------------------------------------
// Helpers
// ---------------------------------------------------------------------------
__device__ __forceinline__ void mma_f32acc(float* d, const uint32_t* a, const uint32_t* b) {
    asm volatile(
        "mma.sync.aligned.m16n8k16.row.col.f32.f16.f16.f32 "
        "{%0,%1,%2,%3}, {%4,%5,%6,%7}, {%8,%9}, {%0,%1,%2,%3};"
        : "+f"(d[0]), "+f"(d[1]), "+f"(d[2]), "+f"(d[3])
        : "r"(a[0]), "r"(a[1]), "r"(a[2]), "r"(a[3]), "r"(b[0]), "r"(b[1]));
}
__device__ __forceinline__ void mma_f16acc(uint32_t* d, const uint32_t* a, const uint32_t* b) {
    asm volatile(
        "mma.sync.aligned.m16n8k16.row.col.f16.f16.f16.f16 "
        "{%0,%1}, {%2,%3,%4,%5}, {%6,%7}, {%0,%1};"
        : "+r"(d[0]), "+r"(d[1])
        : "r"(a[0]), "r"(a[1]), "r"(a[2]), "r"(a[3]), "r"(b[0]), "r"(b[1]));
}
#define LDSM4(r0, r1, r2, r3, addr) \
    asm volatile("ldmatrix.sync.aligned.m8n8.x4.shared.b16 {%0,%1,%2,%3}, [%4];" \
                 : "=r"(r0), "=r"(r1), "=r"(r2), "=r"(r3) : "r"(addr))

// fp16 split with scaled lo plane: x = h + l * 2^-11
__device__ __forceinline__ void split2(float x, __half& h, __half& l) {
    h = __float2half_rn(x);
    l = __float2half_rn((x - __half2float(h)) * LO_SCALE);
}
__device__ __forceinline__ uint64_t pack4h(__half a, __half b, __half c, __half d) {
    union { __half h[4]; uint64_t u; } u;
    u.h[0] = a; u.h[1] = b; u.h[2] = c; u.h[3] = d;
    return u.u;
}
__device__ __forceinline__ uint32_t pack2h(__half a, __half b) {
    union { __half h[2]; uint32_t u; } u;
    u.h[0] = a; u.h[1] = b;
    return u.u;
}
__device__ __forceinline__ uint32_t smem_u32(const void* p) {
    uint32_t a;
    asm("{ .reg .u64 t; cvta.to.shared.u64 t, %1; cvt.u32.u64 %0, t; }"
        : "=r"(a) : "l"(p));
    return a;
}
__device__ __forceinline__ void cp16(uint32_t dst, const void* src) {
    asm volatile("cp.async.cg.shared.global [%0], [%1], 16;"
                 :: "r"(dst), "l"(src));
}
#define CP_COMMIT() asm volatile("cp.async.commit_group;" ::: "memory")
#define CP_WAIT1()  asm volatile("cp.async.wait_group 1;" ::: "memory")
#define CP_WAIT0()  asm volatile("cp.async.wait_group 0;" ::: "memory")

// smem layout (CTA tile 128m x 64n):
//   Ahi [128][36u32] 18432B, Alo 18432B, Bhi [64][36u32] 9216B, Blo 9216B
#define SROW_B  144
#define PLANE_A 18432
#define PLANE_B 9216
#define OFF_AL  PLANE_A
#define OFF_BH  (2 * PLANE_A)
#define OFF_BL  (2 * PLANE_A + PLANE_B)
#define BUF_BYTES (2 * PLANE_A + 2 * PLANE_B)   // 55296
#define SM_TOTAL  (2 * BUF_BYTES)               // 110592 -> 2 CTAs/SM

#define NTHREADS 256

// ---------------------------------------------------------------------------
// fp16 split GEMM on HMMA: C[M,Npad] = op(A@B + bias)
// CROSS=true : 3 products (hh fp32 acc; h.l'+l'.h shared fp16 acc, lo scaled 2^11)
// CROSS=false: 1 product (hh fp32 acc only).
// CTA tile 128x64, BK=64, 256 threads (8 warps = 4M x 2N, warp tile 32x32),
// double-buffered cp.async, ldmatrix loads. 2 CTAs/SM.
// ---------------------------------------------------------------------------
template<int KCHUNKS, bool CROSS, bool BIAS, bool RELU, bool SPLIT_OUT, bool FUSE>
__global__ __launch_bounds__(NTHREADS, 2)
void tc_gemm(const __half* __restrict__ Ahi,
             const __half* __restrict__ Alo,
             const uint32_t* __restrict__ Bh,
             const uint32_t* __restrict__ Bl,
             const float* __restrict__ bias,
             float* __restrict__ C,
             float* __restrict__ Cpl,
             __half* __restrict__ Chi,
             __half* __restrict__ Clo,
             int N) {
    constexpr int K = KCHUNKS * 64;
    constexpr int KH = K / 2;
    extern __shared__ char smem[];
    const uint32_t sb = smem_u32(smem);

    const int tid = threadIdx.x, wid = tid >> 5, lid = tid & 31;
    const int gid = lid >> 2, tig = lid & 3;
    const int mw = (wid & 3) * 32;      // 4 M-warps over 128
    const int nw = (wid >> 2) * 32;     // 2 N-warps over 64
    const int m0 = blockIdx.y * 128, n0 = blockIdx.x * 64;

    uint32_t aoff[2], boff[2];
#pragma unroll
    for (int mat = 0; mat < 2; mat++) {
        const int r = mw + mat * 16 + (lid & 15);
        const int kc = (lid >> 4) * 4;
        aoff[mat] = (uint32_t)(r * 36 + kc) * 4;
    }
#pragma unroll
    for (int p = 0; p < 2; p++) {
        const int r = nw + p * 16 + (lid & 7) + ((lid & 16) >> 1);
        const int kc = ((lid >> 3) & 1) * 4;
        boff[p] = (uint32_t)(r * 36 + kc) * 4;
    }

    float acc[2][4][4];
    uint32_t accx[2][4][2];
#pragma unroll
    for (int i = 0; i < 2; i++)
#pragma unroll
        for (int j = 0; j < 4; j++) {
#pragma unroll
            for (int q = 0; q < 4; q++) acc[i][j][q] = 0.0f;
            accx[i][j][0] = 0u; accx[i][j][1] = 0u;
        }

    auto fill = [&](int c, uint32_t boffb) {
        const int k0 = c * 64;
        // A planes: 128 rows x 8 x 16B = 1024 ops -> 4 iters @ 256 threads
#pragma unroll
        for (int i = 0; i < 4; i++) {
            const int idx = tid + i * NTHREADS;
            const int row = idx >> 3, c8 = idx & 7;
            const uint32_t d = sb + boffb + row * SROW_B + c8 * 16;
            const size_t g = (size_t)(m0 + row) * K + k0 + c8 * 8;
            cp16(d, Ahi + g);
            if (CROSS) cp16(d + OFF_AL, Alo + g);
        }
        // B planes: 64 rows x 8 x 16B = 512 ops -> 2 iters
#pragma unroll
        for (int i = 0; i < 2; i++) {
            const int idx = tid + i * NTHREADS;
            const int row = idx >> 3, c8 = idx & 7;
            const uint32_t d = sb + boffb + OFF_BH + row * SROW_B + c8 * 16;
            const size_t g = (size_t)(n0 + row) * KH + (k0 >> 1) + c8 * 4;
            cp16(d, Bh + g);
            if (CROSS) cp16(d + (OFF_BL - OFF_BH), Bl + g);
        }
    };

    fill(0, 0);
    CP_COMMIT();

    for (int c = 0; c < KCHUNKS; c++) {
        if (c + 1 < KCHUNKS) {
            fill(c + 1, (uint32_t)((c + 1) & 1) * BUF_BYTES);
            CP_COMMIT();
            CP_WAIT1();
        } else {
            CP_WAIT0();
        }
        __syncthreads();

        const uint32_t bufb = sb + (uint32_t)(c & 1) * BUF_BYTES;

#pragma unroll
        for (int ks = 0; ks < 4; ks++) {
            const uint32_t kbB = ks * 32;
            uint32_t ah[2][4], al[2][4], bfh[4][2], bfl[4][2];
#pragma unroll
            for (int mat = 0; mat < 2; mat++) {
                LDSM4(ah[mat][0], ah[mat][1], ah[mat][2], ah[mat][3],
                      bufb + aoff[mat] + kbB);
                if (CROSS)
                    LDSM4(al[mat][0], al[mat][1], al[mat][2], al[mat][3],
                          bufb + OFF_AL + aoff[mat] + kbB);
            }
#pragma unroll
            for (int p = 0; p < 2; p++) {
                LDSM4(bfh[2 * p][0], bfh[2 * p][1], bfh[2 * p + 1][0], bfh[2 * p + 1][1],
                      bufb + OFF_BH + boff[p] + kbB);
                if (CROSS)
                    LDSM4(bfl[2 * p][0], bfl[2 * p][1], bfl[2 * p + 1][0], bfl[2 * p + 1][1],
                          bufb + OFF_BL + boff[p] + kbB);
            }
#pragma unroll
            for (int mat = 0; mat < 2; mat++)
#pragma unroll
                for (int nat = 0; nat < 4; nat++) {
                    mma_f32acc(acc[mat][nat], ah[mat], bfh[nat]);
                    if (CROSS) {
                        mma_f16acc(accx[mat][nat], ah[mat], bfl[nat]);
                        mma_f16acc(accx[mat][nat], al[mat], bfh[nat]);
                    }
                }
        }
        __syncthreads();
    }

    // ---- epilogue
#pragma unroll
    for (int mat = 0; mat < 2; mat++) {
        const int r0 = m0 + mw + mat * 16 + gid;
#pragma unroll
        for (int nat = 0; nat < 4; nat++) {
            const int n = n0 + nw + nat * 8 + tig * 2;
            float c0 = acc[mat][nat][0], c1 = acc[mat][nat][1];
            float c2 = acc[mat][nat][2], c3 = acc[mat][nat][3];
            if (CROSS) {
                const __half2 x01 = *reinterpret_cast<__half2*>(&accx[mat][nat][0]);
                const __half2 x23 = *reinterpret_cast<__half2*>(&accx[mat][nat][1]);
                c0 += LO_INV * __low2float(x01);
                c1 += LO_INV * __high2float(x01);
                c2 += LO_INV * __low2float(x23);
                c3 += LO_INV * __high2float(x23);
            }
            if (BIAS) {
                const float bv0 = (n < N) ? bias[n] : 0.0f;
                const float bv1 = (n + 1 < N) ? bias[n + 1] : 0.0f;
                c0 += bv0; c1 += bv1; c2 += bv0; c3 += bv1;
            }
            if (RELU) {
                c0 = fmaxf(c0, 0.0f); c1 = fmaxf(c1, 0.0f);
                c2 = fmaxf(c2, 0.0f); c3 = fmaxf(c3, 0.0f);
            }
            if (FUSE) {
                auto route = [&](int row, int col, float v) {
                    if (col < 128) {
                        if (col < NBINS) C[(size_t)row * NBINS + col] = v;
                    } else {
                        const int nc = col - 128;
                        if (nc < NBINS * NPAT) Cpl[(size_t)row * (NBINS * NPAT) + nc] = v;
                    }
                };
                route(r0, n, c0);     route(r0, n + 1, c1);
                route(r0 + 8, n, c2); route(r0 + 8, n + 1, c3);
            } else if (SPLIT_OUT) {
                __half h0, l0, h1, l1;
                split2(c0, h0, l0); split2(c1, h1, l1);
                *(uint32_t*)(Chi + (size_t)r0 * N + n) = pack2h(h0, h1);
                *(uint32_t*)(Clo + (size_t)r0 * N + n) = pack2h(l0, l1);
                split2(c2, h0, l0); split2(c3, h1, l1);
                *(uint32_t*)(Chi + (size_t)(r0 + 8) * N + n) = pack2h(h0, h1);
                *(uint32_t*)(Clo + (size_t)(r0 + 8) * N + n) = pack2h(l0, l1);
            } else {
                *(float2*)(C + (size_t)r0 * N + n) = make_float2(c0, c1);
                *(float2*)(C + (size_t)(r0 + 8) * N + n) = make_float2(c2, c3);
            }
        }
    }
}

// ---------------------------------------------------------------------------
// Fused prep: one launch does feature split + W1/W2 packs + concat pack.
// ---------------------------------------------------------------------------
#define PREP_S0 (BATCH * IN_DIM / 4)
#define PREP_S1 (1024 * (IN_DIM / 2))
#define PREP_S2 (512 * (BELLY / 2))
#define PREP_S3 (NCAT * (SCALE_D / 2))
#define PREP_TOTAL (PREP_S0 + PREP_S1 + PREP_S2 + PREP_S3)

__global__ __launch_bounds__(256)
void k_prep(const float* __restrict__ feat,
            __half* __restrict__ fh, __half* __restrict__ fl,
            const float* __restrict__ W1, uint32_t* __restrict__ w1h, uint32_t* __restrict__ w1l,
            const float* __restrict__ W2, uint32_t* __restrict__ w2h, uint32_t* __restrict__ w2l,
            const float* __restrict__ Wt, const float* __restrict__ bt,
            const float* __restrict__ Wp, const float* __restrict__ bp,
            uint32_t* __restrict__ wch, float* __restrict__ bcat) {
    const int gidx = blockIdx.x * blockDim.x + threadIdx.x;
    if (gidx < PREP_S0) {
        const float4 v = ((const float4*)feat)[gidx];
        __half h0, l0, h1, l1, h2, l2, h3, l3;
        split2(v.x, h0, l0); split2(v.y, h1, l1);
        split2(v.z, h2, l2); split2(v.w, h3, l3);
        ((uint64_t*)fh)[gidx] = pack4h(h0, h1, h2, h3);
        ((uint64_t*)fl)[gidx] = pack4h(l0, l1, l2, l3);
    } else if (gidx < PREP_S0 + PREP_S1) {
        const int idx = gidx - PREP_S0;
        const int kh = IN_DIM / 2;
        const int n = idx / kh, kp = idx - n * kh;
        const float v0 = W1[(size_t)(2 * kp) * BELLY + n];
        const float v1 = W1[(size_t)(2 * kp + 1) * BELLY + n];
        __half h0, l0, h1, l1;
        split2(v0, h0, l0); split2(v1, h1, l1);
        w1h[idx] = pack2h(h0, h1);
        w1l[idx] = pack2h(l0, l1);
    } else if (gidx < PREP_S0 + PREP_S1 + PREP_S2) {
        const int idx = gidx - PREP_S0 - PREP_S1;
        const int kh = BELLY / 2;
        const int n = idx / kh, kp = idx - n * kh;
        const float v0 = W2[(size_t)(2 * kp) * SCALE_D + n];
        const float v1 = W2[(size_t)(2 * kp + 1) * SCALE_D + n];
        __half h0, l0, h1, l1;
        split2(v0, h0, l0); split2(v1, h1, l1);
        w2h[idx] = pack2h(h0, h1);
        w2l[idx] = pack2h(l0, l1);
    } else if (gidx < PREP_TOTAL) {
        const int idx = gidx - PREP_S0 - PREP_S1 - PREP_S2;
        const int kh = SCALE_D / 2;
        const int r = idx / kh, kp = idx - r * kh;
        const float* W; int n, N;
        if (r < 128) { W = Wt; n = r; N = NBINS; }
        else         { W = Wp; n = r - 128; N = NBINS * NPAT; }
        float v0 = 0.0f, v1 = 0.0f;
        if (n < N) {
            v0 = W[(size_t)(2 * kp) * N + n];
            v1 = W[(size_t)(2 * kp + 1) * N + n];
        }
        wch[idx] = pack2h(__float2half_rn(v0), __float2half_rn(v1));
        if (kp == 0)
            bcat[r] = (r < 128) ? ((n < NBINS) ? bt[n] : 0.0f)
                                : ((n < NBINS * NPAT) ? bp[n] : 0.0f);
    }
}

// ---------------------------------------------------------------------------
// Exact timestep class + single-block max reduction
// ---------------------------------------------------------------------------
__device__ __forceinline__ int ts_class(int ts) {
    int c = ts / 10;
    return min(max(c, 0), NBINS - 1);
}
__global__ __launch_bounds__(1024)
void k_maxclass(const int* __restrict__ ts) {
    __shared__ int s[32];
    int local = 0;
#pragma unroll
    for (int i = 0; i < BATCH / 1024; i++)
        local = max(local, ts_class(ts[threadIdx.x + i * 1024]));
#pragma unroll
    for (int o = 16; o; o >>= 1)
        local = max(local, __shfl_xor_sync(0xffffffffu, local, o));
    if ((threadIdx.x & 31) == 0) s[threadIdx.x >> 5] = local;
    __syncthreads();
    if (threadIdx.x < 32) {
        int v = s[threadIdx.x];
#pragma unroll
        for (int o = 16; o; o >>= 1)
            v = max(v, __shfl_xor_sync(0xffffffffu, v, o));
        if (threadIdx.x == 0) g_maxclass = v;
    }
}

// ---------------------------------------------------------------------------
// Row normalize: one WARP per row; writes z (fp32), z splits (fp16), and dot.
// ---------------------------------------------------------------------------
__global__ __launch_bounds__(256)
void k_norm(const float* __restrict__ zraw,
            const float* __restrict__ w_pos,
            float* __restrict__ out_z,
            __half* __restrict__ zh,
            __half* __restrict__ zl,
            float* __restrict__ out_dot) {
    const int lid = threadIdx.x & 31;
    const int row = blockIdx.x * 8 + (threadIdx.x >> 5);

    const float4* zr = (const float4*)(zraw + (size_t)row * SCALE_D);
    const float4* wp = (const float4*)w_pos;

    float4 zv[4];
    float ss = 0.0f;
#pragma unroll
    for (int i = 0; i < 4; i++) {
        zv[i] = zr[lid + 32 * i];
        ss += zv[i].x * zv[i].x + zv[i].y * zv[i].y +
              zv[i].z * zv[i].z + zv[i].w * zv[i].w;
    }
#pragma unroll
    for (int o = 16; o; o >>= 1)
        ss += __shfl_xor_sync(0xffffffffu, ss, o);

    const float nrm = fmaxf(__fsqrt_rn(ss), 1e-12f);

    float4* zo = (float4*)(out_z + (size_t)row * SCALE_D);
    float dd = 0.0f;
#pragma unroll
    for (int i = 0; i < 4; i++) {
        float4 o;
        const float4 wv = wp[lid + 32 * i];
        o.x = __fdiv_rn(zv[i].x, nrm);
        o.y = __fdiv_rn(zv[i].y, nrm);
        o.z = __fdiv_rn(zv[i].z, nrm);
        o.w = __fdiv_rn(zv[i].w, nrm);
        zo[lid + 32 * i] = o;
        __half h0, l0, h1, l1, h2, l2, h3, l3;
        split2(o.x, h0, l0); split2(o.y, h1, l1);
        split2(o.z, h2, l2); split2(o.w, h3, l3);
        const size_t e = (size_t)row * SCALE_D + (lid + 32 * i) * 4;
        *(uint64_t*)(zh + e) = pack4h(h0, h1, h2, h3);
        *(uint64_t*)(zl + e) = pack4h(l0, l1, l2, l3);
        dd += o.x * wv.x + o.y * wv.y + o.z * wv.z + o.w * wv.w;
    }
#pragma unroll
    for (int o = 16; o; o >>= 1)
        dd += __shfl_xor_sync(0xffffffffu, dd, o);

    if (lid == 0) out_dot[row] = dd;
}

// ---------------------------------------------------------------------------
// Cantor staircase: one THREAD per row (dense warps).
// ---------------------------------------------------------------------------
__global__ __launch_bounds__(256)
void k_cantor(const float* __restrict__ dot,
              const float* __restrict__ b_pos,
              const float* __restrict__ alpha_p,
              const int* __restrict__ timesteps,
              float* __restrict__ out_tc,
              float* __restrict__ out_cv) {
    const int row = blockIdx.x * blockDim.x + threadIdx.x;
    if (row >= BATCH) return;

    const float tot_dd = dot[row];
    const int cls = ts_class(timesteps[row]);

    const int max_pos = g_maxclass + 1;
    const float denom = (float)max(max_pos - 1, 1);
    const float pos_f = (float)cls;
    float x = (max_pos > 1) ? __fdiv_rn(pos_f, denom) : pos_f;
    x = fminf(fmaxf(x, XMINF), XMAXF);

    const float pre = __fadd_rn(tot_dd, b_pos[0]);
    const float shift = __fmul_rn((float)tanh((double)pre), 0.3f);
    x = fminf(fmaxf(__fadd_rn(x, shift), XMINF), XMAXF);

    const double alpha = (double)(*alpha_p);
    const float tau_d = __fadd_rn(0.25f, 1e-8f);
    double Cx = 0.0;
    double w = 0.5;
#pragma unroll
    for (int L = 0; L < 12; L++) {
        const float y = __fmul_rn(x, 3.0f);
        const float d0 = __fadd_rn(y, -0.5f);
        const float d1 = __fadd_rn(y, -1.5f);
        const float d2 = __fadd_rn(y, -2.5f);
        const float l0 = __fdiv_rn(-__fmul_rn(d0, d0), tau_d);
        const float l1 = __fdiv_rn(-__fmul_rn(d1, d1), tau_d);
        const float l2 = __fdiv_rn(-__fmul_rn(d2, d2), tau_d);
        const float m = fmaxf(l0, fmaxf(l1, l2));
        const double e0 = exp((double)__fadd_rn(l0, -m));
        const double e1 = exp((double)__fadd_rn(l1, -m));
        const double e2 = exp((double)__fadd_rn(l2, -m));
        const double inv_s = 1.0 / (e0 + e1 + e2);
        const double bit = e1 * inv_s * alpha + e2 * inv_s;
        Cx += bit * w;
        w *= 0.5;
        x = __fadd_rn(y, -floorf(y));
    }
    out_tc[row] = (float)cls;
    float cvf = (float)Cx;
    out_cv[row] = fminf(fmaxf(cvf, 0.0f), 1.0f);
}

// ---------------------------------------------------------------------------
// Launch (7 graph nodes)
// ---------------------------------------------------------------------------
extern "C" void kernel_launch(void* const* d_in, const int* in_sizes, int n_in,
                              void* d_out, int out_size) {
    const float* features = (const float*)d_in[0];
    const int*   timesteps = (const int*)d_in[1];
    const float* W1    = (const float*)d_in[2];
    const float* b1    = (const float*)d_in[3];
    const float* W2    = (const float*)d_in[4];
    const float* Wt    = (const float*)d_in[5];
    const float* bt    = (const float*)d_in[6];
    const float* Wp    = (const float*)d_in[7];
    const float* bp    = (const float*)d_in[8];
    const float* w_pos = (const float*)d_in[9];
    const float* b_pos = (const float*)d_in[10];
    const float* alpha = (const float*)d_in[11];

    float* out = (float*)d_out;
    float* out_z  = out + Z_OFF;
    float* out_tl = out + TL_OFF;
    float* out_pl = out + PL_OFF;
    float* out_tc = out + TC_OFF;
    float* out_cv = out + CV_OFF;

    __half *fh, *fl, *hh, *hl, *zh, *zl;
    uint32_t *w1h, *w1l, *w2h, *w2l, *wch;
    float *zraw, *dot, *bcat;
    cudaGetSymbolAddress((void**)&fh, g_fh);   cudaGetSymbolAddress((void**)&fl, g_fl);
    cudaGetSymbolAddress((void**)&hh, g_hh);   cudaGetSymbolAddress((void**)&hl, g_hl);
    cudaGetSymbolAddress((void**)&zh, g_zh);   cudaGetSymbolAddress((void**)&zl, g_zl);
    cudaGetSymbolAddress((void**)&w1h, g_w1h); cudaGetSymbolAddress((void**)&w1l, g_w1l);
    cudaGetSymbolAddress((void**)&w2h, g_w2h); cudaGetSymbolAddress((void**)&w2l, g_w2l);
    cudaGetSymbolAddress((void**)&wch, g_wch);
    cudaGetSymbolAddress((void**)&bcat, g_bcat);
    cudaGetSymbolAddress((void**)&zraw, g_zraw);
    cudaGetSymbolAddress((void**)&dot, g_dot);

    auto* g1  = tc_gemm<IN_DIM / 64, true, true, true, true, false>;
    auto* g2  = tc_gemm<BELLY / 64, true, false, false, false, false>;
    auto* g34 = tc_gemm<SCALE_D / 64, false, true, false, false, true>;
    cudaFuncSetAttribute(g1,  cudaFuncAttributeMaxDynamicSharedMemorySize, SM_TOTAL);
    cudaFuncSetAttribute(g2,  cudaFuncAttributeMaxDynamicSharedMemorySize, SM_TOTAL);
    cudaFuncSetAttribute(g34, cudaFuncAttributeMaxDynamicSharedMemorySize, SM_TOTAL);

    // 1) max timestep class
    k_maxclass<<<1, 1024>>>(timesteps);

    // 2) fused prep
    k_prep<<<(PREP_TOTAL + 255) / 256, 256>>>(
        features, fh, fl, W1, w1h, w1l, W2, w2h, w2l,
        Wt, bt, Wp, bp, wch, bcat);

    // 3) GEMM1: h(split) = relu(features @ W1 + b1)   [tiles 16 x 128]
    g1<<<dim3(BELLY / 64, BATCH / 128), NTHREADS, SM_TOTAL>>>(
        fh, fl, w1h, w1l, b1, nullptr, nullptr, hh, hl, BELLY);

    // 4) GEMM2: zraw = h @ W2                          [tiles 8 x 128]
    g2<<<dim3(SCALE_D / 64, BATCH / 128), NTHREADS, SM_TOTAL>>>(
        hh, hl, w2h, w2l, nullptr, zraw, nullptr, nullptr, nullptr, SCALE_D);

    // 5) normalize (warp/row, dense)
    k_norm<<<BATCH / 8, 256>>>(zraw, w_pos, out_z, zh, zl, dot);

    // 6) fused GEMM3+GEMM4 (single product)            [tiles 18 x 128]
    g34<<<dim3(NCAT / 64, BATCH / 128), NTHREADS, SM_TOTAL>>>(
        zh, nullptr, wch, nullptr, bcat, out_tl, out_pl, nullptr, nullptr, NCAT);

    // 7) cantor (thread/row, dense)
    k_cantor<<<(BATCH + 255) / 256, 256>>>(dot, b_pos, alpha, timesteps, out_tc, out_cv);
}

// round 16
// speedup vs baseline: 2.1384x; 1.0151x over previous
#include <cuda_runtime.h>
#include <cuda_fp16.h>
#include <math.h>
#include <stdint.h>

// Problem constants
#define BATCH   16384
#define IN_DIM  1280
#define BELLY   1024
#define SCALE_D 512
#define NBINS   100
#define NPAT    10
#define NCAT    1152   // 128 (Wt slot) + 1024 (Wp slot)

// Output layout (float32, concatenated flattened tuple)
#define Z_OFF   ((size_t)0)
#define TL_OFF  ((size_t)BATCH * SCALE_D)
#define PL_OFF  (TL_OFF + (size_t)BATCH * NBINS)
#define TC_OFF  (PL_OFF + (size_t)BATCH * NBINS * NPAT)
#define CV_OFF  (TC_OFF + (size_t)BATCH)

#define XMINF 1e-6f
#define XMAXF ((float)(1.0 - 1e-6))
#define LO_SCALE 2048.0f
#define LO_INV   4.8828125e-4f   // 2^-11, exact

// ---------------------------------------------------------------------------
// Scratch (device globals: allocation-guard safe)
// ---------------------------------------------------------------------------
__device__ __half g_fh[(size_t)BATCH * IN_DIM];
__device__ __half g_fl[(size_t)BATCH * IN_DIM];
__device__ __half g_hh[(size_t)BATCH * BELLY];
__device__ __half g_hl[(size_t)BATCH * BELLY];
__device__ __half g_zh[(size_t)BATCH * SCALE_D];
__device__ __half g_zl[(size_t)BATCH * SCALE_D];
__device__ float  g_zraw[(size_t)BATCH * SCALE_D];
// n-major, k-pair-contiguous weight planes: u32[Npad][K/2]
__device__ uint32_t g_w1h[1024 * (IN_DIM / 2)];
__device__ uint32_t g_w1l[1024 * (IN_DIM / 2)];
__device__ uint32_t g_w2h[512 * (BELLY / 2)];
__device__ uint32_t g_w2l[512 * (BELLY / 2)];
__device__ uint32_t g_wch[NCAT * (SCALE_D / 2)];   // concat Wt|Wp (hi only)
__device__ float    g_bcat[NCAT];
__device__ float    g_dot[BATCH];
__device__ int      g_maxclass;

// ---------------------------------------------------------------------------
// Helpers
// ---------------------------------------------------------------------------
__device__ __forceinline__ void mma_f32acc(float* d, const uint32_t* a, const uint32_t* b) {
    asm volatile(
        "mma.sync.aligned.m16n8k16.row.col.f32.f16.f16.f32 "
        "{%0,%1,%2,%3}, {%4,%5,%6,%7}, {%8,%9}, {%0,%1,%2,%3};"
        : "+f"(d[0]), "+f"(d[1]), "+f"(d[2]), "+f"(d[3])
        : "r"(a[0]), "r"(a[1]), "r"(a[2]), "r"(a[3]), "r"(b[0]), "r"(b[1]));
}
__device__ __forceinline__ void mma_f16acc(uint32_t* d, const uint32_t* a, const uint32_t* b) {
    asm volatile(
        "mma.sync.aligned.m16n8k16.row.col.f16.f16.f16.f16 "
        "{%0,%1}, {%2,%3,%4,%5}, {%6,%7}, {%0,%1};"
        : "+r"(d[0]), "+r"(d[1])
        : "r"(a[0]), "r"(a[1]), "r"(a[2]), "r"(a[3]), "r"(b[0]), "r"(b[1]));
}
#define LDSM4(r0, r1, r2, r3, addr) \
    asm volatile("ldmatrix.sync.aligned.m8n8.x4.shared.b16 {%0,%1,%2,%3}, [%4];" \
                 : "=r"(r0), "=r"(r1), "=r"(r2), "=r"(r3) : "r"(addr))

// fp16 split with scaled lo plane: x = h + l * 2^-11
__device__ __forceinline__ void split2(float x, __half& h, __half& l) {
    h = __float2half_rn(x);
    l = __float2half_rn((x - __half2float(h)) * LO_SCALE);
}
__device__ __forceinline__ uint64_t pack4h(__half a, __half b, __half c, __half d) {
    union { __half h[4]; uint64_t u; } u;
    u.h[0] = a; u.h[1] = b; u.h[2] = c; u.h[3] = d;
    return u.u;
}
__device__ __forceinline__ uint32_t pack2h(__half a, __half b) {
    union { __half h[2]; uint32_t u; } u;
    u.h[0] = a; u.h[1] = b;
    return u.u;
}
__device__ __forceinline__ uint32_t smem_u32(const void* p) {
    uint32_t a;
    asm("{ .reg .u64 t; cvta.to.shared.u64 t, %1; cvt.u32.u64 %0, t; }"
        : "=r"(a) : "l"(p));
    return a;
}
__device__ __forceinline__ void cp16(uint32_t dst, const void* src) {
    asm volatile("cp.async.cg.shared.global [%0], [%1], 16;"
                 :: "r"(dst), "l"(src));
}
#define CP_COMMIT() asm volatile("cp.async.commit_group;" ::: "memory")
#define CP_WAIT0()  asm volatile("cp.async.wait_group 0;" ::: "memory")

// smem layout (CTA tile 128m x 64n):
//   Ahi [128][36u32] 18432B, Alo 18432B, Bhi [64][36u32] 9216B, Blo 9216B
#define SROW_B  144
#define PLANE_A 18432
#define PLANE_B 9216
#define OFF_AL  PLANE_A
#define OFF_BH  (2 * PLANE_A)
#define OFF_BL  (2 * PLANE_A + PLANE_B)
#define BUF_BYTES (2 * PLANE_A + 2 * PLANE_B)   // 55296
#define SM_TOTAL  (2 * BUF_BYTES)               // 110592 -> 2 CTAs/SM

#define NTHREADS 256

// ---------------------------------------------------------------------------
// fp16 split GEMM on HMMA: C[M,Npad] = op(A@B + bias)
// CROSS=true : 3 products (hh fp32 acc; h.l'+l'.h shared fp16 acc, lo scaled 2^11)
// CROSS=false: 1 product (hh fp32 acc only).
// CTA tile 128x64, BK=64, 256 threads (8 warps = 4M x 2N, warp tile 32x32),
// 2 CTAs/SM, single-sync double-buffered cp.async pipeline.
// ---------------------------------------------------------------------------
template<int KCHUNKS, bool CROSS, bool BIAS, bool RELU, bool SPLIT_OUT, bool FUSE>
__global__ __launch_bounds__(NTHREADS, 2)
void tc_gemm(const __half* __restrict__ Ahi,
             const __half* __restrict__ Alo,
             const uint32_t* __restrict__ Bh,
             const uint32_t* __restrict__ Bl,
             const float* __restrict__ bias,
             float* __restrict__ C,
             float* __restrict__ Cpl,
             __half* __restrict__ Chi,
             __half* __restrict__ Clo,
             int N) {
    constexpr int K = KCHUNKS * 64;
    constexpr int KH = K / 2;
    extern __shared__ char smem[];
    const uint32_t sb = smem_u32(smem);

    const int tid = threadIdx.x, wid = tid >> 5, lid = tid & 31;
    const int gid = lid >> 2, tig = lid & 3;
    const int mw = (wid & 3) * 32;      // 4 M-warps over 128
    const int nw = (wid >> 2) * 32;     // 2 N-warps over 64
    const int m0 = blockIdx.y * 128, n0 = blockIdx.x * 64;

    uint32_t aoff[2], boff[2];
#pragma unroll
    for (int mat = 0; mat < 2; mat++) {
        const int r = mw + mat * 16 + (lid & 15);
        const int kc = (lid >> 4) * 4;
        aoff[mat] = (uint32_t)(r * 36 + kc) * 4;
    }
#pragma unroll
    for (int p = 0; p < 2; p++) {
        const int r = nw + p * 16 + (lid & 7) + ((lid & 16) >> 1);
        const int kc = ((lid >> 3) & 1) * 4;
        boff[p] = (uint32_t)(r * 36 + kc) * 4;
    }

    float acc[2][4][4];
    uint32_t accx[2][4][2];
#pragma unroll
    for (int i = 0; i < 2; i++)
#pragma unroll
        for (int j = 0; j < 4; j++) {
#pragma unroll
            for (int q = 0; q < 4; q++) acc[i][j][q] = 0.0f;
            accx[i][j][0] = 0u; accx[i][j][1] = 0u;
        }

    auto fill = [&](int c, uint32_t boffb) {
        const int k0 = c * 64;
#pragma unroll
        for (int i = 0; i < 4; i++) {
            const int idx = tid + i * NTHREADS;
            const int row = idx >> 3, c8 = idx & 7;
            const uint32_t d = sb + boffb + row * SROW_B + c8 * 16;
            const size_t g = (size_t)(m0 + row) * K + k0 + c8 * 8;
            cp16(d, Ahi + g);
            if (CROSS) cp16(d + OFF_AL, Alo + g);
        }
#pragma unroll
        for (int i = 0; i < 2; i++) {
            const int idx = tid + i * NTHREADS;
            const int row = idx >> 3, c8 = idx & 7;
            const uint32_t d = sb + boffb + OFF_BH + row * SROW_B + c8 * 16;
            const size_t g = (size_t)(n0 + row) * KH + (k0 >> 1) + c8 * 4;
            cp16(d, Bh + g);
            if (CROSS) cp16(d + (OFF_BL - OFF_BH), Bl + g);
        }
    };

    fill(0, 0);
    CP_COMMIT();

    for (int c = 0; c < KCHUNKS; c++) {
        CP_WAIT0();          // this warp's fill(c) landed
        __syncthreads();     // publishes all warps' fills; all past compute(c-1)
        if (c + 1 < KCHUNKS) {
            fill(c + 1, (uint32_t)((c + 1) & 1) * BUF_BYTES);   // overlaps compute(c)
            CP_COMMIT();
        }

        const uint32_t bufb = sb + (uint32_t)(c & 1) * BUF_BYTES;

#pragma unroll
        for (int ks = 0; ks < 4; ks++) {
            const uint32_t kbB = ks * 32;
            uint32_t ah[2][4], al[2][4], bfh[4][2], bfl[4][2];
#pragma unroll
            for (int mat = 0; mat < 2; mat++) {
                LDSM4(ah[mat][0], ah[mat][1], ah[mat][2], ah[mat][3],
                      bufb + aoff[mat] + kbB);
                if (CROSS)
                    LDSM4(al[mat][0], al[mat][1], al[mat][2], al[mat][3],
                          bufb + OFF_AL + aoff[mat] + kbB);
            }
#pragma unroll
            for (int p = 0; p < 2; p++) {
                LDSM4(bfh[2 * p][0], bfh[2 * p][1], bfh[2 * p + 1][0], bfh[2 * p + 1][1],
                      bufb + OFF_BH + boff[p] + kbB);
                if (CROSS)
                    LDSM4(bfl[2 * p][0], bfl[2 * p][1], bfl[2 * p + 1][0], bfl[2 * p + 1][1],
                          bufb + OFF_BL + boff[p] + kbB);
            }
#pragma unroll
            for (int mat = 0; mat < 2; mat++)
#pragma unroll
                for (int nat = 0; nat < 4; nat++) {
                    mma_f32acc(acc[mat][nat], ah[mat], bfh[nat]);
                    if (CROSS) {
                        mma_f16acc(accx[mat][nat], ah[mat], bfl[nat]);
                        mma_f16acc(accx[mat][nat], al[mat], bfh[nat]);
                    }
                }
        }
    }

    // ---- epilogue
#pragma unroll
    for (int mat = 0; mat < 2; mat++) {
        const int r0 = m0 + mw + mat * 16 + gid;
#pragma unroll
        for (int nat = 0; nat < 4; nat++) {
            const int n = n0 + nw + nat * 8 + tig * 2;
            float c0 = acc[mat][nat][0], c1 = acc[mat][nat][1];
            float c2 = acc[mat][nat][2], c3 = acc[mat][nat][3];
            if (CROSS) {
                const __half2 x01 = *reinterpret_cast<__half2*>(&accx[mat][nat][0]);
                const __half2 x23 = *reinterpret_cast<__half2*>(&accx[mat][nat][1]);
                c0 += LO_INV * __low2float(x01);
                c1 += LO_INV * __high2float(x01);
                c2 += LO_INV * __low2float(x23);
                c3 += LO_INV * __high2float(x23);
            }
            if (BIAS) {
                const float bv0 = (n < N) ? bias[n] : 0.0f;
                const float bv1 = (n + 1 < N) ? bias[n + 1] : 0.0f;
                c0 += bv0; c1 += bv1; c2 += bv0; c3 += bv1;
            }
            if (RELU) {
                c0 = fmaxf(c0, 0.0f); c1 = fmaxf(c1, 0.0f);
                c2 = fmaxf(c2, 0.0f); c3 = fmaxf(c3, 0.0f);
            }
            if (FUSE) {
                auto route = [&](int row, int col, float v) {
                    if (col < 128) {
                        if (col < NBINS) C[(size_t)row * NBINS + col] = v;
                    } else {
                        const int nc = col - 128;
                        if (nc < NBINS * NPAT) Cpl[(size_t)row * (NBINS * NPAT) + nc] = v;
                    }
                };
                route(r0, n, c0);     route(r0, n + 1, c1);
                route(r0 + 8, n, c2); route(r0 + 8, n + 1, c3);
            } else if (SPLIT_OUT) {
                __half h0, l0, h1, l1;
                split2(c0, h0, l0); split2(c1, h1, l1);
                *(uint32_t*)(Chi + (size_t)r0 * N + n) = pack2h(h0, h1);
                *(uint32_t*)(Clo + (size_t)r0 * N + n) = pack2h(l0, l1);
                split2(c2, h0, l0); split2(c3, h1, l1);
                *(uint32_t*)(Chi + (size_t)(r0 + 8) * N + n) = pack2h(h0, h1);
                *(uint32_t*)(Clo + (size_t)(r0 + 8) * N + n) = pack2h(l0, l1);
            } else {
                *(float2*)(C + (size_t)r0 * N + n) = make_float2(c0, c1);
                *(float2*)(C + (size_t)(r0 + 8) * N + n) = make_float2(c2, c3);
            }
        }
    }
}

// ---------------------------------------------------------------------------
// Fused prep: one launch does feature split + W1/W2 packs + concat pack.
// ---------------------------------------------------------------------------
#define PREP_S0 (BATCH * IN_DIM / 4)
#define PREP_S1 (1024 * (IN_DIM / 2))
#define PREP_S2 (512 * (BELLY / 2))
#define PREP_S3 (NCAT * (SCALE_D / 2))
#define PREP_TOTAL (PREP_S0 + PREP_S1 + PREP_S2 + PREP_S3)

__global__ __launch_bounds__(256)
void k_prep(const float* __restrict__ feat,
            __half* __restrict__ fh, __half* __restrict__ fl,
            const float* __restrict__ W1, uint32_t* __restrict__ w1h, uint32_t* __restrict__ w1l,
            const float* __restrict__ W2, uint32_t* __restrict__ w2h, uint32_t* __restrict__ w2l,
            const float* __restrict__ Wt, const float* __restrict__ bt,
            const float* __restrict__ Wp, const float* __restrict__ bp,
            uint32_t* __restrict__ wch, float* __restrict__ bcat) {
    const int gidx = blockIdx.x * blockDim.x + threadIdx.x;
    if (gidx < PREP_S0) {
        const float4 v = ((const float4*)feat)[gidx];
        __half h0, l0, h1, l1, h2, l2, h3, l3;
        split2(v.x, h0, l0); split2(v.y, h1, l1);
        split2(v.z, h2, l2); split2(v.w, h3, l3);
        ((uint64_t*)fh)[gidx] = pack4h(h0, h1, h2, h3);
        ((uint64_t*)fl)[gidx] = pack4h(l0, l1, l2, l3);
    } else if (gidx < PREP_S0 + PREP_S1) {
        const int idx = gidx - PREP_S0;
        const int kh = IN_DIM / 2;
        const int n = idx / kh, kp = idx - n * kh;
        const float v0 = W1[(size_t)(2 * kp) * BELLY + n];
        const float v1 = W1[(size_t)(2 * kp + 1) * BELLY + n];
        __half h0, l0, h1, l1;
        split2(v0, h0, l0); split2(v1, h1, l1);
        w1h[idx] = pack2h(h0, h1);
        w1l[idx] = pack2h(l0, l1);
    } else if (gidx < PREP_S0 + PREP_S1 + PREP_S2) {
        const int idx = gidx - PREP_S0 - PREP_S1;
        const int kh = BELLY / 2;
        const int n = idx / kh, kp = idx - n * kh;
        const float v0 = W2[(size_t)(2 * kp) * SCALE_D + n];
        const float v1 = W2[(size_t)(2 * kp + 1) * SCALE_D + n];
        __half h0, l0, h1, l1;
        split2(v0, h0, l0); split2(v1, h1, l1);
        w2h[idx] = pack2h(h0, h1);
        w2l[idx] = pack2h(l0, l1);
    } else if (gidx < PREP_TOTAL) {
        const int idx = gidx - PREP_S0 - PREP_S1 - PREP_S2;
        const int kh = SCALE_D / 2;
        const int r = idx / kh, kp = idx - r * kh;
        const float* W; int n, N;
        if (r < 128) { W = Wt; n = r; N = NBINS; }
        else         { W = Wp; n = r - 128; N = NBINS * NPAT; }
        float v0 = 0.0f, v1 = 0.0f;
        if (n < N) {
            v0 = W[(size_t)(2 * kp) * N + n];
            v1 = W[(size_t)(2 * kp + 1) * N + n];
        }
        wch[idx] = pack2h(__float2half_rn(v0), __float2half_rn(v1));
        if (kp == 0)
            bcat[r] = (r < 128) ? ((n < NBINS) ? bt[n] : 0.0f)
                                : ((n < NBINS * NPAT) ? bp[n] : 0.0f);
    }
}

// ---------------------------------------------------------------------------
// Exact timestep class + single-block max reduction
// ---------------------------------------------------------------------------
__device__ __forceinline__ int ts_class(int ts) {
    int c = ts / 10;
    return min(max(c, 0), NBINS - 1);
}
__global__ __launch_bounds__(1024)
void k_maxclass(const int* __restrict__ ts) {
    __shared__ int s[32];
    int local = 0;
#pragma unroll
    for (int i = 0; i < BATCH / 1024; i++)
        local = max(local, ts_class(ts[threadIdx.x + i * 1024]));
#pragma unroll
    for (int o = 16; o; o >>= 1)
        local = max(local, __shfl_xor_sync(0xffffffffu, local, o));
    if ((threadIdx.x & 31) == 0) s[threadIdx.x >> 5] = local;
    __syncthreads();
    if (threadIdx.x < 32) {
        int v = s[threadIdx.x];
#pragma unroll
        for (int o = 16; o; o >>= 1)
            v = max(v, __shfl_xor_sync(0xffffffffu, v, o));
        if (threadIdx.x == 0) g_maxclass = v;
    }
}

// ---------------------------------------------------------------------------
// Row normalize: one WARP per row; writes z (fp32), z splits (fp16), and dot.
// ---------------------------------------------------------------------------
__global__ __launch_bounds__(256)
void k_norm(const float* __restrict__ zraw,
            const float* __restrict__ w_pos,
            float* __restrict__ out_z,
            __half* __restrict__ zh,
            __half* __restrict__ zl,
            float* __restrict__ out_dot) {
    const int lid = threadIdx.x & 31;
    const int row = blockIdx.x * 8 + (threadIdx.x >> 5);

    const float4* zr = (const float4*)(zraw + (size_t)row * SCALE_D);
    const float4* wp = (const float4*)w_pos;

    float4 zv[4];
    float ss = 0.0f;
#pragma unroll
    for (int i = 0; i < 4; i++) {
        zv[i] = zr[lid + 32 * i];
        ss += zv[i].x * zv[i].x + zv[i].y * zv[i].y +
              zv[i].z * zv[i].z + zv[i].w * zv[i].w;
    }
#pragma unroll
    for (int o = 16; o; o >>= 1)
        ss += __shfl_xor_sync(0xffffffffu, ss, o);

    const float nrm = fmaxf(__fsqrt_rn(ss), 1e-12f);

    float4* zo = (float4*)(out_z + (size_t)row * SCALE_D);
    float dd = 0.0f;
#pragma unroll
    for (int i = 0; i < 4; i++) {
        float4 o;
        const float4 wv = wp[lid + 32 * i];
        o.x = __fdiv_rn(zv[i].x, nrm);
        o.y = __fdiv_rn(zv[i].y, nrm);
        o.z = __fdiv_rn(zv[i].z, nrm);
        o.w = __fdiv_rn(zv[i].w, nrm);
        zo[lid + 32 * i] = o;
        __half h0, l0, h1, l1, h2, l2, h3, l3;
        split2(o.x, h0, l0); split2(o.y, h1, l1);
        split2(o.z, h2, l2); split2(o.w, h3, l3);
        const size_t e = (size_t)row * SCALE_D + (lid + 32 * i) * 4;
        *(uint64_t*)(zh + e) = pack4h(h0, h1, h2, h3);
        *(uint64_t*)(zl + e) = pack4h(l0, l1, l2, l3);
        dd += o.x * wv.x + o.y * wv.y + o.z * wv.z + o.w * wv.w;
    }
#pragma unroll
    for (int o = 16; o; o >>= 1)
        dd += __shfl_xor_sync(0xffffffffu, dd, o);

    if (lid == 0) out_dot[row] = dd;
}

// ---------------------------------------------------------------------------
// Cantor staircase: one THREAD per row (dense warps).
// ---------------------------------------------------------------------------
__global__ __launch_bounds__(256)
void k_cantor(const float* __restrict__ dot,
              const float* __restrict__ b_pos,
              const float* __restrict__ alpha_p,
              const int* __restrict__ timesteps,
              float* __restrict__ out_tc,
              float* __restrict__ out_cv) {
    const int row = blockIdx.x * blockDim.x + threadIdx.x;
    if (row >= BATCH) return;

    const float tot_dd = dot[row];
    const int cls = ts_class(timesteps[row]);

    const int max_pos = g_maxclass + 1;
    const float denom = (float)max(max_pos - 1, 1);
    const float pos_f = (float)cls;
    float x = (max_pos > 1) ? __fdiv_rn(pos_f, denom) : pos_f;
    x = fminf(fmaxf(x, XMINF), XMAXF);

    const float pre = __fadd_rn(tot_dd, b_pos[0]);
    const float shift = __fmul_rn((float)tanh((double)pre), 0.3f);
    x = fminf(fmaxf(__fadd_rn(x, shift), XMINF), XMAXF);

    const double alpha = (double)(*alpha_p);
    const float tau_d = __fadd_rn(0.25f, 1e-8f);
    double Cx = 0.0;
    double w = 0.5;
#pragma unroll
    for (int L = 0; L < 12; L++) {
        const float y = __fmul_rn(x, 3.0f);
        const float d0 = __fadd_rn(y, -0.5f);
        const float d1 = __fadd_rn(y, -1.5f);
        const float d2 = __fadd_rn(y, -2.5f);
        const float l0 = __fdiv_rn(-__fmul_rn(d0, d0), tau_d);
        const float l1 = __fdiv_rn(-__fmul_rn(d1, d1), tau_d);
        const float l2 = __fdiv_rn(-__fmul_rn(d2, d2), tau_d);
        const float m = fmaxf(l0, fmaxf(l1, l2));
        const double e0 = exp((double)__fadd_rn(l0, -m));
        const double e1 = exp((double)__fadd_rn(l1, -m));
        const double e2 = exp((double)__fadd_rn(l2, -m));
        const double inv_s = 1.0 / (e0 + e1 + e2);
        const double bit = e1 * inv_s * alpha + e2 * inv_s;
        Cx += bit * w;
        w *= 0.5;
        x = __fadd_rn(y, -floorf(y));
    }
    out_tc[row] = (float)cls;
    float cvf = (float)Cx;
    out_cv[row] = fminf(fmaxf(cvf, 0.0f), 1.0f);
}

// ---------------------------------------------------------------------------
// Launch (7 graph nodes)
// ---------------------------------------------------------------------------
extern "C" void kernel_launch(void* const* d_in, const int* in_sizes, int n_in,
                              void* d_out, int out_size) {
    const float* features = (const float*)d_in[0];
    const int*   timesteps = (const int*)d_in[1];
    const float* W1    = (const float*)d_in[2];
    const float* b1    = (const float*)d_in[3];
    const float* W2    = (const float*)d_in[4];
    const float* Wt    = (const float*)d_in[5];
    const float* bt    = (const float*)d_in[6];
    const float* Wp    = (const float*)d_in[7];
    const float* bp    = (const float*)d_in[8];
    const float* w_pos = (const float*)d_in[9];
    const float* b_pos = (const float*)d_in[10];
    const float* alpha = (const float*)d_in[11];

    float* out = (float*)d_out;
    float* out_z  = out + Z_OFF;
    float* out_tl = out + TL_OFF;
    float* out_pl = out + PL_OFF;
    float* out_tc = out + TC_OFF;
    float* out_cv = out + CV_OFF;

    __half *fh, *fl, *hh, *hl, *zh, *zl;
    uint32_t *w1h, *w1l, *w2h, *w2l, *wch;
    float *zraw, *dot, *bcat;
    cudaGetSymbolAddress((void**)&fh, g_fh);   cudaGetSymbolAddress((void**)&fl, g_fl);
    cudaGetSymbolAddress((void**)&hh, g_hh);   cudaGetSymbolAddress((void**)&hl, g_hl);
    cudaGetSymbolAddress((void**)&zh, g_zh);   cudaGetSymbolAddress((void**)&zl, g_zl);
    cudaGetSymbolAddress((void**)&w1h, g_w1h); cudaGetSymbolAddress((void**)&w1l, g_w1l);
    cudaGetSymbolAddress((void**)&w2h, g_w2h); cudaGetSymbolAddress((void**)&w2l, g_w2l);
    cudaGetSymbolAddress((void**)&wch, g_wch);
    cudaGetSymbolAddress((void**)&bcat, g_bcat);
    cudaGetSymbolAddress((void**)&zraw, g_zraw);
    cudaGetSymbolAddress((void**)&dot, g_dot);

    auto* g1  = tc_gemm<IN_DIM / 64, true, true, true, true, false>;
    auto* g2  = tc_gemm<BELLY / 64, true, false, false, false, false>;
    auto* g34 = tc_gemm<SCALE_D / 64, false, true, false, false, true>;
    cudaFuncSetAttribute(g1,  cudaFuncAttributeMaxDynamicSharedMemorySize, SM_TOTAL);
    cudaFuncSetAttribute(g2,  cudaFuncAttributeMaxDynamicSharedMemorySize, SM_TOTAL);
    cudaFuncSetAttribute(g34, cudaFuncAttributeMaxDynamicSharedMemorySize, SM_TOTAL);

    // 1) max timestep class
    k_maxclass<<<1, 1024>>>(timesteps);

    // 2) fused prep
    k_prep<<<(PREP_TOTAL + 255) / 256, 256>>>(
        features, fh, fl, W1, w1h, w1l, W2, w2h, w2l,
        Wt, bt, Wp, bp, wch, bcat);

    // 3) GEMM1: h(split) = relu(features @ W1 + b1)
    g1<<<dim3(BELLY / 64, BATCH / 128), NTHREADS, SM_TOTAL>>>(
        fh, fl, w1h, w1l, b1, nullptr, nullptr, hh, hl, BELLY);

    // 4) GEMM2: zraw = h @ W2
    g2<<<dim3(SCALE_D / 64, BATCH / 128), NTHREADS, SM_TOTAL>>>(
        hh, hl, w2h, w2l, nullptr, zraw, nullptr, nullptr, nullptr, SCALE_D);

    // 5) normalize (warp/row, dense)
    k_norm<<<BATCH / 8, 256>>>(zraw, w_pos, out_z, zh, zl, dot);

    // 6) fused GEMM3+GEMM4 (single product)
    g34<<<dim3(NCAT / 64, BATCH / 128), NTHREADS, SM_TOTAL>>>(
        zh, nullptr, wch, nullptr, bcat, out_tl, out_pl, nullptr, nullptr, NCAT);

    // 7) cantor (thread/row, dense)
    k_cantor<<<(BATCH + 255) / 256, 256>>>(dot, b_pos, alpha, timesteps, out_tc, out_cv);
}

// round 17
// speedup vs baseline: 2.1739x; 1.0166x over previous
#include <cuda_runtime.h>
#include <cuda_fp16.h>
#include <math.h>
#include <stdint.h>

// Problem constants
#define BATCH   16384
#define IN_DIM  1280
#define BELLY   1024
#define SCALE_D 512
#define NBINS   100
#define NPAT    10
#define NCAT    1152   // 128 (Wt slot) + 1024 (Wp slot)

// Output layout (float32, concatenated flattened tuple)
#define Z_OFF   ((size_t)0)
#define TL_OFF  ((size_t)BATCH * SCALE_D)
#define PL_OFF  (TL_OFF + (size_t)BATCH * NBINS)
#define TC_OFF  (PL_OFF + (size_t)BATCH * NBINS * NPAT)
#define CV_OFF  (TC_OFF + (size_t)BATCH)

#define XMINF 1e-6f
#define XMAXF ((float)(1.0 - 1e-6))
#define LO_SCALE 2048.0f
#define LO_INV   4.8828125e-4f   // 2^-11, exact

// ---------------------------------------------------------------------------
// Scratch (device globals: allocation-guard safe)
// ---------------------------------------------------------------------------
__device__ __half g_fh[(size_t)BATCH * IN_DIM];
__device__ __half g_fl[(size_t)BATCH * IN_DIM];
__device__ __half g_hh[(size_t)BATCH * BELLY];
__device__ __half g_hl[(size_t)BATCH * BELLY];
__device__ __half g_zh[(size_t)BATCH * SCALE_D];
__device__ __half g_zl[(size_t)BATCH * SCALE_D];
__device__ float  g_zraw[(size_t)BATCH * SCALE_D];
// n-major, k-pair-contiguous weight planes: u32[Npad][K/2]
__device__ uint32_t g_w1h[1024 * (IN_DIM / 2)];
__device__ uint32_t g_w1l[1024 * (IN_DIM / 2)];
__device__ uint32_t g_w2h[512 * (BELLY / 2)];
__device__ uint32_t g_w2l[512 * (BELLY / 2)];
__device__ uint32_t g_wch[NCAT * (SCALE_D / 2)];   // concat Wt|Wp (hi only)
__device__ float    g_bcat[NCAT];
__device__ float    g_dot[BATCH];
__device__ int      g_maxclass;

// ---------------------------------------------------------------------------
// Helpers
// ---------------------------------------------------------------------------
__device__ __forceinline__ void mma_f32acc(float* d, const uint32_t* a, const uint32_t* b) {
    asm volatile(
        "mma.sync.aligned.m16n8k16.row.col.f32.f16.f16.f32 "
        "{%0,%1,%2,%3}, {%4,%5,%6,%7}, {%8,%9}, {%0,%1,%2,%3};"
        : "+f"(d[0]), "+f"(d[1]), "+f"(d[2]), "+f"(d[3])
        : "r"(a[0]), "r"(a[1]), "r"(a[2]), "r"(a[3]), "r"(b[0]), "r"(b[1]));
}
__device__ __forceinline__ void mma_f16acc(uint32_t* d, const uint32_t* a, const uint32_t* b) {
    asm volatile(
        "mma.sync.aligned.m16n8k16.row.col.f16.f16.f16.f16 "
        "{%0,%1}, {%2,%3,%4,%5}, {%6,%7}, {%0,%1};"
        : "+r"(d[0]), "+r"(d[1])
        : "r"(a[0]), "r"(a[1]), "r"(a[2]), "r"(a[3]), "r"(b[0]), "r"(b[1]));
}
#define LDSM4(r0, r1, r2, r3, addr) \
    asm volatile("ldmatrix.sync.aligned.m8n8.x4.shared.b16 {%0,%1,%2,%3}, [%4];" \
                 : "=r"(r0), "=r"(r1), "=r"(r2), "=r"(r3) : "r"(addr))

// fp16 split with scaled lo plane: x = h + l * 2^-11
__device__ __forceinline__ void split2(float x, __half& h, __half& l) {
    h = __float2half_rn(x);
    l = __float2half_rn((x - __half2float(h)) * LO_SCALE);
}
__device__ __forceinline__ uint64_t pack4h(__half a, __half b, __half c, __half d) {
    union { __half h[4]; uint64_t u; } u;
    u.h[0] = a; u.h[1] = b; u.h[2] = c; u.h[3] = d;
    return u.u;
}
__device__ __forceinline__ uint32_t pack2h(__half a, __half b) {
    union { __half h[2]; uint32_t u; } u;
    u.h[0] = a; u.h[1] = b;
    return u.u;
}
__device__ __forceinline__ uint32_t smem_u32(const void* p) {
    uint32_t a;
    asm("{ .reg .u64 t; cvta.to.shared.u64 t, %1; cvt.u32.u64 %0, t; }"
        : "=r"(a) : "l"(p));
    return a;
}
__device__ __forceinline__ void cp16(uint32_t dst, const void* src) {
    asm volatile("cp.async.cg.shared.global [%0], [%1], 16;"
                 :: "r"(dst), "l"(src));
}
#define CP_COMMIT() asm volatile("cp.async.commit_group;" ::: "memory")
#define CP_WAIT0()  asm volatile("cp.async.wait_group 0;" ::: "memory")

// smem planes (CTA tile 128m x 64n)
#define SROW_B  144
#define PLANE_A 18432
#define PLANE_B 9216

#define NTHREADS 256

// ---------------------------------------------------------------------------
// fp16 split GEMM on HMMA: C[M,Npad] = op(A@B + bias)
// CROSS=true : 3 products (hh fp32 acc; h.l'+l'.h shared fp16 acc, lo scaled 2^11)
//              smem = 2 x 55296 -> 2 CTAs/SM
// CROSS=false: 1 product (hh fp32 acc) — compact smem = 2 x 27648 -> 4 CTAs/SM
// CTA tile 128x64, BK=64, 256 threads (8 warps = 4M x 2N, warp tile 32x32),
// single-sync double-buffered cp.async pipeline.
// ---------------------------------------------------------------------------
template<int KCHUNKS, bool CROSS, bool BIAS, bool RELU, bool SPLIT_OUT, bool FUSE>
__global__ __launch_bounds__(NTHREADS, CROSS ? 2 : 4)
void tc_gemm(const __half* __restrict__ Ahi,
             const __half* __restrict__ Alo,
             const uint32_t* __restrict__ Bh,
             const uint32_t* __restrict__ Bl,
             const float* __restrict__ bias,
             float* __restrict__ C,
             float* __restrict__ Cpl,
             __half* __restrict__ Chi,
             __half* __restrict__ Clo,
             int N) {
    constexpr int K = KCHUNKS * 64;
    constexpr int KH = K / 2;
    constexpr uint32_t OFFAL = PLANE_A;                                   // CROSS only
    constexpr uint32_t OFFBH = CROSS ? 2u * PLANE_A : (uint32_t)PLANE_A;
    constexpr uint32_t OFFBL = OFFBH + PLANE_B;                           // CROSS only
    constexpr uint32_t BUFB  = CROSS ? (2u * PLANE_A + 2u * PLANE_B)
                                     : ((uint32_t)PLANE_A + PLANE_B);
    extern __shared__ char smem[];
    const uint32_t sb = smem_u32(smem);

    const int tid = threadIdx.x, wid = tid >> 5, lid = tid & 31;
    const int gid = lid >> 2, tig = lid & 3;
    const int mw = (wid & 3) * 32;      // 4 M-warps over 128
    const int nw = (wid >> 2) * 32;     // 2 N-warps over 64
    const int m0 = blockIdx.y * 128, n0 = blockIdx.x * 64;

    uint32_t aoff[2], boff[2];
#pragma unroll
    for (int mat = 0; mat < 2; mat++) {
        const int r = mw + mat * 16 + (lid & 15);
        const int kc = (lid >> 4) * 4;
        aoff[mat] = (uint32_t)(r * 36 + kc) * 4;
    }
#pragma unroll
    for (int p = 0; p < 2; p++) {
        const int r = nw + p * 16 + (lid & 7) + ((lid & 16) >> 1);
        const int kc = ((lid >> 3) & 1) * 4;
        boff[p] = (uint32_t)(r * 36 + kc) * 4;
    }

    float acc[2][4][4];
    uint32_t accx[2][4][2];
#pragma unroll
    for (int i = 0; i < 2; i++)
#pragma unroll
        for (int j = 0; j < 4; j++) {
#pragma unroll
            for (int q = 0; q < 4; q++) acc[i][j][q] = 0.0f;
            accx[i][j][0] = 0u; accx[i][j][1] = 0u;
        }

    auto fill = [&](int c, uint32_t boffb) {
        const int k0 = c * 64;
#pragma unroll
        for (int i = 0; i < 4; i++) {
            const int idx = tid + i * NTHREADS;
            const int row = idx >> 3, c8 = idx & 7;
            const uint32_t d = sb + boffb + row * SROW_B + c8 * 16;
            const size_t g = (size_t)(m0 + row) * K + k0 + c8 * 8;
            cp16(d, Ahi + g);
            if (CROSS) cp16(d + OFFAL, Alo + g);
        }
#pragma unroll
        for (int i = 0; i < 2; i++) {
            const int idx = tid + i * NTHREADS;
            const int row = idx >> 3, c8 = idx & 7;
            const uint32_t d = sb + boffb + OFFBH + row * SROW_B + c8 * 16;
            const size_t g = (size_t)(n0 + row) * KH + (k0 >> 1) + c8 * 4;
            cp16(d, Bh + g);
            if (CROSS) cp16(d + PLANE_B, Bl + g);
        }
    };

    fill(0, 0);
    CP_COMMIT();

    for (int c = 0; c < KCHUNKS; c++) {
        CP_WAIT0();          // this warp's fill(c) landed
        __syncthreads();     // publishes all warps' fills; all past compute(c-1)
        if (c + 1 < KCHUNKS) {
            fill(c + 1, (uint32_t)((c + 1) & 1) * BUFB);   // overlaps compute(c)
            CP_COMMIT();
        }

        const uint32_t bufb = sb + (uint32_t)(c & 1) * BUFB;

#pragma unroll
        for (int ks = 0; ks < 4; ks++) {
            const uint32_t kbB = ks * 32;
            uint32_t ah[2][4], al[2][4], bfh[4][2], bfl[4][2];
#pragma unroll
            for (int mat = 0; mat < 2; mat++) {
                LDSM4(ah[mat][0], ah[mat][1], ah[mat][2], ah[mat][3],
                      bufb + aoff[mat] + kbB);
                if (CROSS)
                    LDSM4(al[mat][0], al[mat][1], al[mat][2], al[mat][3],
                          bufb + OFFAL + aoff[mat] + kbB);
            }
#pragma unroll
            for (int p = 0; p < 2; p++) {
                LDSM4(bfh[2 * p][0], bfh[2 * p][1], bfh[2 * p + 1][0], bfh[2 * p + 1][1],
                      bufb + OFFBH + boff[p] + kbB);
                if (CROSS)
                    LDSM4(bfl[2 * p][0], bfl[2 * p][1], bfl[2 * p + 1][0], bfl[2 * p + 1][1],
                          bufb + OFFBL + boff[p] + kbB);
            }
#pragma unroll
            for (int mat = 0; mat < 2; mat++)
#pragma unroll
                for (int nat = 0; nat < 4; nat++) {
                    mma_f32acc(acc[mat][nat], ah[mat], bfh[nat]);
                    if (CROSS) {
                        mma_f16acc(accx[mat][nat], ah[mat], bfl[nat]);
                        mma_f16acc(accx[mat][nat], al[mat], bfh[nat]);
                    }
                }
        }
    }

    // ---- epilogue
#pragma unroll
    for (int mat = 0; mat < 2; mat++) {
        const int r0 = m0 + mw + mat * 16 + gid;
#pragma unroll
        for (int nat = 0; nat < 4; nat++) {
            const int n = n0 + nw + nat * 8 + tig * 2;
            float c0 = acc[mat][nat][0], c1 = acc[mat][nat][1];
            float c2 = acc[mat][nat][2], c3 = acc[mat][nat][3];
            if (CROSS) {
                const __half2 x01 = *reinterpret_cast<__half2*>(&accx[mat][nat][0]);
                const __half2 x23 = *reinterpret_cast<__half2*>(&accx[mat][nat][1]);
                c0 += LO_INV * __low2float(x01);
                c1 += LO_INV * __high2float(x01);
                c2 += LO_INV * __low2float(x23);
                c3 += LO_INV * __high2float(x23);
            }
            if (BIAS) {
                const float bv0 = (n < N) ? bias[n] : 0.0f;
                const float bv1 = (n + 1 < N) ? bias[n + 1] : 0.0f;
                c0 += bv0; c1 += bv1; c2 += bv0; c3 += bv1;
            }
            if (RELU) {
                c0 = fmaxf(c0, 0.0f); c1 = fmaxf(c1, 0.0f);
                c2 = fmaxf(c2, 0.0f); c3 = fmaxf(c3, 0.0f);
            }
            if (FUSE) {
                auto route = [&](int row, int col, float v) {
                    if (col < 128) {
                        if (col < NBINS) C[(size_t)row * NBINS + col] = v;
                    } else {
                        const int nc = col - 128;
                        if (nc < NBINS * NPAT) Cpl[(size_t)row * (NBINS * NPAT) + nc] = v;
                    }
                };
                route(r0, n, c0);     route(r0, n + 1, c1);
                route(r0 + 8, n, c2); route(r0 + 8, n + 1, c3);
            } else if (SPLIT_OUT) {
                __half h0, l0, h1, l1;
                split2(c0, h0, l0); split2(c1, h1, l1);
                *(uint32_t*)(Chi + (size_t)r0 * N + n) = pack2h(h0, h1);
                *(uint32_t*)(Clo + (size_t)r0 * N + n) = pack2h(l0, l1);
                split2(c2, h0, l0); split2(c3, h1, l1);
                *(uint32_t*)(Chi + (size_t)(r0 + 8) * N + n) = pack2h(h0, h1);
                *(uint32_t*)(Clo + (size_t)(r0 + 8) * N + n) = pack2h(l0, l1);
            } else {
                *(float2*)(C + (size_t)r0 * N + n) = make_float2(c0, c1);
                *(float2*)(C + (size_t)(r0 + 8) * N + n) = make_float2(c2, c3);
            }
        }
    }
}

// ---------------------------------------------------------------------------
// Fused prep: one launch does feature split + W1/W2 packs + concat pack.
// ---------------------------------------------------------------------------
#define PREP_S0 (BATCH * IN_DIM / 4)
#define PREP_S1 (1024 * (IN_DIM / 2))
#define PREP_S2 (512 * (BELLY / 2))
#define PREP_S3 (NCAT * (SCALE_D / 2))
#define PREP_TOTAL (PREP_S0 + PREP_S1 + PREP_S2 + PREP_S3)

__global__ __launch_bounds__(256)
void k_prep(const float* __restrict__ feat,
            __half* __restrict__ fh, __half* __restrict__ fl,
            const float* __restrict__ W1, uint32_t* __restrict__ w1h, uint32_t* __restrict__ w1l,
            const float* __restrict__ W2, uint32_t* __restrict__ w2h, uint32_t* __restrict__ w2l,
            const float* __restrict__ Wt, const float* __restrict__ bt,
            const float* __restrict__ Wp, const float* __restrict__ bp,
            uint32_t* __restrict__ wch, float* __restrict__ bcat) {
    const int gidx = blockIdx.x * blockDim.x + threadIdx.x;
    if (gidx < PREP_S0) {
        const float4 v = ((const float4*)feat)[gidx];
        __half h0, l0, h1, l1, h2, l2, h3, l3;
        split2(v.x, h0, l0); split2(v.y, h1, l1);
        split2(v.z, h2, l2); split2(v.w, h3, l3);
        ((uint64_t*)fh)[gidx] = pack4h(h0, h1, h2, h3);
        ((uint64_t*)fl)[gidx] = pack4h(l0, l1, l2, l3);
    } else if (gidx < PREP_S0 + PREP_S1) {
        const int idx = gidx - PREP_S0;
        const int kh = IN_DIM / 2;
        const int n = idx / kh, kp = idx - n * kh;
        const float v0 = W1[(size_t)(2 * kp) * BELLY + n];
        const float v1 = W1[(size_t)(2 * kp + 1) * BELLY + n];
        __half h0, l0, h1, l1;
        split2(v0, h0, l0); split2(v1, h1, l1);
        w1h[idx] = pack2h(h0, h1);
        w1l[idx] = pack2h(l0, l1);
    } else if (gidx < PREP_S0 + PREP_S1 + PREP_S2) {
        const int idx = gidx - PREP_S0 - PREP_S1;
        const int kh = BELLY / 2;
        const int n = idx / kh, kp = idx - n * kh;
        const float v0 = W2[(size_t)(2 * kp) * SCALE_D + n];
        const float v1 = W2[(size_t)(2 * kp + 1) * SCALE_D + n];
        __half h0, l0, h1, l1;
        split2(v0, h0, l0); split2(v1, h1, l1);
        w2h[idx] = pack2h(h0, h1);
        w2l[idx] = pack2h(l0, l1);
    } else if (gidx < PREP_TOTAL) {
        const int idx = gidx - PREP_S0 - PREP_S1 - PREP_S2;
        const int kh = SCALE_D / 2;
        const int r = idx / kh, kp = idx - r * kh;
        const float* W; int n, N;
        if (r < 128) { W = Wt; n = r; N = NBINS; }
        else         { W = Wp; n = r - 128; N = NBINS * NPAT; }
        float v0 = 0.0f, v1 = 0.0f;
        if (n < N) {
            v0 = W[(size_t)(2 * kp) * N + n];
            v1 = W[(size_t)(2 * kp + 1) * N + n];
        }
        wch[idx] = pack2h(__float2half_rn(v0), __float2half_rn(v1));
        if (kp == 0)
            bcat[r] = (r < 128) ? ((n < NBINS) ? bt[n] : 0.0f)
                                : ((n < NBINS * NPAT) ? bp[n] : 0.0f);
    }
}

// ---------------------------------------------------------------------------
// Exact timestep class + single-block max reduction
// ---------------------------------------------------------------------------
__device__ __forceinline__ int ts_class(int ts) {
    int c = ts / 10;
    return min(max(c, 0), NBINS - 1);
}
__global__ __launch_bounds__(1024)
void k_maxclass(const int* __restrict__ ts) {
    __shared__ int s[32];
    int local = 0;
#pragma unroll
    for (int i = 0; i < BATCH / 1024; i++)
        local = max(local, ts_class(ts[threadIdx.x + i * 1024]));
#pragma unroll
    for (int o = 16; o; o >>= 1)
        local = max(local, __shfl_xor_sync(0xffffffffu, local, o));
    if ((threadIdx.x & 31) == 0) s[threadIdx.x >> 5] = local;
    __syncthreads();
    if (threadIdx.x < 32) {
        int v = s[threadIdx.x];
#pragma unroll
        for (int o = 16; o; o >>= 1)
            v = max(v, __shfl_xor_sync(0xffffffffu, v, o));
        if (threadIdx.x == 0) g_maxclass = v;
    }
}

// ---------------------------------------------------------------------------
// Row normalize: one WARP per row; writes z (fp32), z splits (fp16), and dot.
// ---------------------------------------------------------------------------
__global__ __launch_bounds__(256)
void k_norm(const float* __restrict__ zraw,
            const float* __restrict__ w_pos,
            float* __restrict__ out_z,
            __half* __restrict__ zh,
            __half* __restrict__ zl,
            float* __restrict__ out_dot) {
    const int lid = threadIdx.x & 31;
    const int row = blockIdx.x * 8 + (threadIdx.x >> 5);

    const float4* zr = (const float4*)(zraw + (size_t)row * SCALE_D);
    const float4* wp = (const float4*)w_pos;

    float4 zv[4];
    float ss = 0.0f;
#pragma unroll
    for (int i = 0; i < 4; i++) {
        zv[i] = zr[lid + 32 * i];
        ss += zv[i].x * zv[i].x + zv[i].y * zv[i].y +
              zv[i].z * zv[i].z + zv[i].w * zv[i].w;
    }
#pragma unroll
    for (int o = 16; o; o >>= 1)
        ss += __shfl_xor_sync(0xffffffffu, ss, o);

    const float nrm = fmaxf(__fsqrt_rn(ss), 1e-12f);

    float4* zo = (float4*)(out_z + (size_t)row * SCALE_D);
    float dd = 0.0f;
#pragma unroll
    for (int i = 0; i < 4; i++) {
        float4 o;
        const float4 wv = wp[lid + 32 * i];
        o.x = __fdiv_rn(zv[i].x, nrm);
        o.y = __fdiv_rn(zv[i].y, nrm);
        o.z = __fdiv_rn(zv[i].z, nrm);
        o.w = __fdiv_rn(zv[i].w, nrm);
        zo[lid + 32 * i] = o;
        __half h0, l0, h1, l1, h2, l2, h3, l3;
        split2(o.x, h0, l0); split2(o.y, h1, l1);
        split2(o.z, h2, l2); split2(o.w, h3, l3);
        const size_t e = (size_t)row * SCALE_D + (lid + 32 * i) * 4;
        *(uint64_t*)(zh + e) = pack4h(h0, h1, h2, h3);
        *(uint64_t*)(zl + e) = pack4h(l0, l1, l2, l3);
        dd += o.x * wv.x + o.y * wv.y + o.z * wv.z + o.w * wv.w;
    }
#pragma unroll
    for (int o = 16; o; o >>= 1)
        dd += __shfl_xor_sync(0xffffffffu, dd, o);

    if (lid == 0) out_dot[row] = dd;
}

// ---------------------------------------------------------------------------
// Cantor staircase: one THREAD per row (dense warps).
// ---------------------------------------------------------------------------
__global__ __launch_bounds__(256)
void k_cantor(const float* __restrict__ dot,
              const float* __restrict__ b_pos,
              const float* __restrict__ alpha_p,
              const int* __restrict__ timesteps,
              float* __restrict__ out_tc,
              float* __restrict__ out_cv) {
    const int row = blockIdx.x * blockDim.x + threadIdx.x;
    if (row >= BATCH) return;

    const float tot_dd = dot[row];
    const int cls = ts_class(timesteps[row]);

    const int max_pos = g_maxclass + 1;
    const float denom = (float)max(max_pos - 1, 1);
    const float pos_f = (float)cls;
    float x = (max_pos > 1) ? __fdiv_rn(pos_f, denom) : pos_f;
    x = fminf(fmaxf(x, XMINF), XMAXF);

    const float pre = __fadd_rn(tot_dd, b_pos[0]);
    const float shift = __fmul_rn((float)tanh((double)pre), 0.3f);
    x = fminf(fmaxf(__fadd_rn(x, shift), XMINF), XMAXF);

    const double alpha = (double)(*alpha_p);
    const float tau_d = __fadd_rn(0.25f, 1e-8f);
    double Cx = 0.0;
    double w = 0.5;
#pragma unroll
    for (int L = 0; L < 12; L++) {
        const float y = __fmul_rn(x, 3.0f);
        const float d0 = __fadd_rn(y, -0.5f);
        const float d1 = __fadd_rn(y, -1.5f);
        const float d2 = __fadd_rn(y, -2.5f);
        const float l0 = __fdiv_rn(-__fmul_rn(d0, d0), tau_d);
        const float l1 = __fdiv_rn(-__fmul_rn(d1, d1), tau_d);
        const float l2 = __fdiv_rn(-__fmul_rn(d2, d2), tau_d);
        const float m = fmaxf(l0, fmaxf(l1, l2));
        const double e0 = exp((double)__fadd_rn(l0, -m));
        const double e1 = exp((double)__fadd_rn(l1, -m));
        const double e2 = exp((double)__fadd_rn(l2, -m));
        const double inv_s = 1.0 / (e0 + e1 + e2);
        const double bit = e1 * inv_s * alpha + e2 * inv_s;
        Cx += bit * w;
        w *= 0.5;
        x = __fadd_rn(y, -floorf(y));
    }
    out_tc[row] = (float)cls;
    float cvf = (float)Cx;
    out_cv[row] = fminf(fmaxf(cvf, 0.0f), 1.0f);
}

// ---------------------------------------------------------------------------
// Launch (7 graph nodes)
// ---------------------------------------------------------------------------
extern "C" void kernel_launch(void* const* d_in, const int* in_sizes, int n_in,
                              void* d_out, int out_size) {
    const float* features = (const float*)d_in[0];
    const int*   timesteps = (const int*)d_in[1];
    const float* W1    = (const float*)d_in[2];
    const float* b1    = (const float*)d_in[3];
    const float* W2    = (const float*)d_in[4];
    const float* Wt    = (const float*)d_in[5];
    const float* bt    = (const float*)d_in[6];
    const float* Wp    = (const float*)d_in[7];
    const float* bp    = (const float*)d_in[8];
    const float* w_pos = (const float*)d_in[9];
    const float* b_pos = (const float*)d_in[10];
    const float* alpha = (const float*)d_in[11];

    float* out = (float*)d_out;
    float* out_z  = out + Z_OFF;
    float* out_tl = out + TL_OFF;
    float* out_pl = out + PL_OFF;
    float* out_tc = out + TC_OFF;
    float* out_cv = out + CV_OFF;

    __half *fh, *fl, *hh, *hl, *zh, *zl;
    uint32_t *w1h, *w1l, *w2h, *w2l, *wch;
    float *zraw, *dot, *bcat;
    cudaGetSymbolAddress((void**)&fh, g_fh);   cudaGetSymbolAddress((void**)&fl, g_fl);
    cudaGetSymbolAddress((void**)&hh, g_hh);   cudaGetSymbolAddress((void**)&hl, g_hl);
    cudaGetSymbolAddress((void**)&zh, g_zh);   cudaGetSymbolAddress((void**)&zl, g_zl);
    cudaGetSymbolAddress((void**)&w1h, g_w1h); cudaGetSymbolAddress((void**)&w1l, g_w1l);
    cudaGetSymbolAddress((void**)&w2h, g_w2h); cudaGetSymbolAddress((void**)&w2l, g_w2l);
    cudaGetSymbolAddress((void**)&wch, g_wch);
    cudaGetSymbolAddress((void**)&bcat, g_bcat);
    cudaGetSymbolAddress((void**)&zraw, g_zraw);
    cudaGetSymbolAddress((void**)&dot, g_dot);

    auto* g1  = tc_gemm<IN_DIM / 64, true, true, true, true, false>;
    auto* g2  = tc_gemm<BELLY / 64, true, false, false, false, false>;
    auto* g34 = tc_gemm<SCALE_D / 64, false, true, false, false, true>;
    const int SMEM_CROSS = 2 * (2 * PLANE_A + 2 * PLANE_B);   // 110592
    const int SMEM_NC    = 2 * (PLANE_A + PLANE_B);           // 55296
    cudaFuncSetAttribute(g1,  cudaFuncAttributeMaxDynamicSharedMemorySize, SMEM_CROSS);
    cudaFuncSetAttribute(g2,  cudaFuncAttributeMaxDynamicSharedMemorySize, SMEM_CROSS);
    cudaFuncSetAttribute(g34, cudaFuncAttributeMaxDynamicSharedMemorySize, SMEM_NC);

    // 1) max timestep class
    k_maxclass<<<1, 1024>>>(timesteps);

    // 2) fused prep
    k_prep<<<(PREP_TOTAL + 255) / 256, 256>>>(
        features, fh, fl, W1, w1h, w1l, W2, w2h, w2l,
        Wt, bt, Wp, bp, wch, bcat);

    // 3) GEMM1: h(split) = relu(features @ W1 + b1)
    g1<<<dim3(BELLY / 64, BATCH / 128), NTHREADS, SMEM_CROSS>>>(
        fh, fl, w1h, w1l, b1, nullptr, nullptr, hh, hl, BELLY);

    // 4) GEMM2: zraw = h @ W2
    g2<<<dim3(SCALE_D / 64, BATCH / 128), NTHREADS, SMEM_CROSS>>>(
        hh, hl, w2h, w2l, nullptr, zraw, nullptr, nullptr, nullptr, SCALE_D);

    // 5) normalize (warp/row, dense)
    k_norm<<<BATCH / 8, 256>>>(zraw, w_pos, out_z, zh, zl, dot);

    // 6) fused GEMM3+GEMM4 (single product, compact smem, 4 CTAs/SM)
    g34<<<dim3(NCAT / 64, BATCH / 128), NTHREADS, SMEM_NC>>>(
        zh, nullptr, wch, nullptr, bcat, out_tl, out_pl, nullptr, nullptr, NCAT);

    // 7) cantor (thread/row, dense)
    k_cantor<<<(BATCH + 255) / 256, 256>>>(dot, b_pos, alpha, timesteps, out_tc, out_cv);
}